// round 5
// baseline (speedup 1.0000x reference)
#include <cuda_runtime.h>
#include <math.h>

#define Bz   64
#define Lz   49
#define ENCD 2048
#define DEC  512
#define ATTD 256
#define VOC  10000
#define Tz   50
#define H3   1536
#define EMBD 512

// ---------------- scratch (device globals; no runtime alloc) ----------------
__device__ float g_enc [Bz*Lz*DEC];     // [B,L,DEC]
__device__ float g_att1[Bz*Lz*ATTD];    // [B,L,ATT]
__device__ float g_Xemb[Tz*Bz*EMBD];    // gathered embeddings, row r = t*B+b
__device__ float g_gie [Tz*Bz*H3];      // emb part of GRU input gates (+b_ih)
__device__ float g_Wihe[DEC*H3];        // W_ih[:, :512]  transposed -> [k][j]
__device__ float g_Wihc[DEC*H3];        // W_ih[:, 512:]  transposed -> [k][j]
__device__ float g_Whh [DEC*H3];        // W_hh transposed -> [k][j]
__device__ float g_h   [Bz*DEC];        // current hidden
__device__ float g_ctx [Bz*DEC];        // attention context
__device__ float g_part[8*Bz*H3];       // split-K partials: [mat(2)*4+split][b][j]
__device__ float g_Hseq[Tz*Bz*DEC];     // h_new per step, row r = t*B+b

// ---------------- init: zero h + gather embeddings ----------------
__global__ void k_init(const int* __restrict__ cap, const float* __restrict__ emb)
{
    int i = blockIdx.x * blockDim.x + threadIdx.x;   // launched with exactly T*B*EMB threads
    if (i < Bz * DEC) g_h[i] = 0.f;
    int d = i & 511;
    int r = i >> 9;            // t*B + b
    int t = r >> 6;
    int b = r & 63;
    int tok = cap[b * Tz + t];
    g_Xemb[i] = emb[(size_t)tok * EMBD + d];
}

// ---------------- one-time weight transposes ----------------
__global__ void k_transpose(const float* __restrict__ W_ih, const float* __restrict__ W_hh)
{
    int i = blockIdx.x * blockDim.x + threadIdx.x;   // over DEC*H3
    if (i >= DEC * H3) return;
    int j = i >> 9;       // 0..1535 (row of torch weight)
    int k = i & 511;      // 0..511
    g_Wihe[k * H3 + j] = W_ih[j * (EMBD + DEC) + k];
    g_Wihc[k * H3 + j] = W_ih[j * (EMBD + DEC) + EMBD + k];
    g_Whh [k * H3 + j] = W_hh[j * DEC + k];
}

// ---------------- generic fp32 GEMM: C[M,N] = A[M,K] @ B[K,N] + bias ----------------
// 128x128 block tile, 8x8 microtile, 256 threads. remap=1 writes fc output as
// out[(b*T + t)*V + n] with row = t*B + b.
__global__ __launch_bounds__(256) void k_gemm(
    const float* __restrict__ A, const float* __restrict__ Bm,
    const float* __restrict__ bias, float* __restrict__ C,
    int M, int N, int K, int remap)
{
    __shared__ float sA[16][132];
    __shared__ float sB[16][128];
    const int tid = threadIdx.x;
    const int tx = tid & 15, ty = tid >> 4;
    const int mb = blockIdx.y << 7;
    const int nb = blockIdx.x << 7;
    float acc[8][8] = {};

    for (int k0 = 0; k0 < K; k0 += 16) {
        #pragma unroll
        for (int u = 0; u < 2; u++) {
            int f = tid + u * 256;
            // A tile: 128 rows x 16 k  (512 float4)
            int arow = f >> 2, akq = (f & 3) << 2;
            float4 av = make_float4(0.f, 0.f, 0.f, 0.f);
            if (mb + arow < M)
                av = *reinterpret_cast<const float4*>(&A[(size_t)(mb + arow) * K + k0 + akq]);
            sA[akq + 0][arow] = av.x; sA[akq + 1][arow] = av.y;
            sA[akq + 2][arow] = av.z; sA[akq + 3][arow] = av.w;
            // B tile: 16 rows x 128 cols (512 float4), guard N
            int brow = f >> 5, bcol = (f & 31) << 2;
            int n = nb + bcol;
            const float* bp = &Bm[(size_t)(k0 + brow) * N + n];
            float4 bv;
            if (n + 3 < N) bv = *reinterpret_cast<const float4*>(bp);
            else {
                bv.x = (n + 0 < N) ? bp[0] : 0.f;
                bv.y = (n + 1 < N) ? bp[1] : 0.f;
                bv.z = (n + 2 < N) ? bp[2] : 0.f;
                bv.w = (n + 3 < N) ? bp[3] : 0.f;
            }
            *reinterpret_cast<float4*>(&sB[brow][bcol]) = bv;
        }
        __syncthreads();
        #pragma unroll
        for (int kk = 0; kk < 16; kk++) {
            float4 a0 = *reinterpret_cast<const float4*>(&sA[kk][ty * 8]);
            float4 a1 = *reinterpret_cast<const float4*>(&sA[kk][ty * 8 + 4]);
            float4 b0 = *reinterpret_cast<const float4*>(&sB[kk][tx * 8]);
            float4 b1 = *reinterpret_cast<const float4*>(&sB[kk][tx * 8 + 4]);
            float av[8] = {a0.x, a0.y, a0.z, a0.w, a1.x, a1.y, a1.z, a1.w};
            float bv[8] = {b0.x, b0.y, b0.z, b0.w, b1.x, b1.y, b1.z, b1.w};
            #pragma unroll
            for (int i = 0; i < 8; i++)
                #pragma unroll
                for (int j = 0; j < 8; j++)
                    acc[i][j] += av[i] * bv[j];
        }
        __syncthreads();
    }

    #pragma unroll
    for (int i = 0; i < 8; i++) {
        int row = mb + ty * 8 + i;
        if (row >= M) break;
        #pragma unroll
        for (int j = 0; j < 8; j++) {
            int col = nb + tx * 8 + j;
            if (col < N) {
                float v = acc[i][j] + bias[col];
                if (remap) {
                    int t = row >> 6, bb = row & 63;
                    C[((size_t)(bb * Tz + t)) * VOC + col] = v;
                } else {
                    C[(size_t)row * N + col] = v;
                }
            }
        }
    }
}

// ---------------- per-step dual GEMM (gi_c and gh), split-K=4 ----------------
// grid (24 n-tiles, 4 k-splits, 2 mats), block 256. Each block: 64x64x128.
__global__ __launch_bounds__(256) void k_stepgemm()
{
    __shared__ float sA[16][68];
    __shared__ float sB[16][64];
    const int tid = threadIdx.x;
    const int tx = tid & 15, ty = tid >> 4;
    const int nb = blockIdx.x << 6;
    const int kbase = blockIdx.y << 7;
    const int z = blockIdx.z;
    const float* A  = z ? g_h   : g_ctx;
    const float* Bw = z ? g_Whh : g_Wihc;
    float* out = &g_part[(size_t)((z * 4 + blockIdx.y) * Bz) * H3];
    float acc[4][4] = {};
    const int arow = tid >> 2, akq = (tid & 3) << 2;
    const int brow = tid >> 4, bcol = (tid & 15) << 2;

    for (int kc = 0; kc < 128; kc += 16) {
        int k0 = kbase + kc;
        float4 av = *reinterpret_cast<const float4*>(&A[arow * DEC + k0 + akq]);
        sA[akq + 0][arow] = av.x; sA[akq + 1][arow] = av.y;
        sA[akq + 2][arow] = av.z; sA[akq + 3][arow] = av.w;
        float4 bv = *reinterpret_cast<const float4*>(&Bw[(size_t)(k0 + brow) * H3 + nb + bcol]);
        *reinterpret_cast<float4*>(&sB[brow][bcol]) = bv;
        __syncthreads();
        #pragma unroll
        for (int kk = 0; kk < 16; kk++) {
            float4 a = *reinterpret_cast<const float4*>(&sA[kk][ty * 4]);
            float4 b = *reinterpret_cast<const float4*>(&sB[kk][tx * 4]);
            float avr[4] = {a.x, a.y, a.z, a.w};
            float bvr[4] = {b.x, b.y, b.z, b.w};
            #pragma unroll
            for (int i = 0; i < 4; i++)
                #pragma unroll
                for (int j = 0; j < 4; j++)
                    acc[i][j] += avr[i] * bvr[j];
        }
        __syncthreads();
    }
    #pragma unroll
    for (int i = 0; i < 4; i++)
        #pragma unroll
        for (int j = 0; j < 4; j++)
            out[(size_t)(ty * 4 + i) * H3 + nb + tx * 4 + j] = acc[i][j];
}

// ---------------- GRU gate combine (reads split-K partials) ----------------
__device__ __forceinline__ float gru_update(int r, int b, int d, const float* __restrict__ b_hh)
{
    const float* gie = &g_gie[(size_t)r * H3];
    float ir = gie[d], iz = gie[DEC + d], in_ = gie[2 * DEC + d];
    float hr = b_hh[d], hz = b_hh[DEC + d], hn = b_hh[2 * DEC + d];
    #pragma unroll
    for (int s = 0; s < 4; s++) {
        const float* p = &g_part[(size_t)(s * Bz + b) * H3];
        ir += p[d]; iz += p[DEC + d]; in_ += p[2 * DEC + d];
        const float* q = &g_part[(size_t)((4 + s) * Bz + b) * H3];
        hr += q[d]; hz += q[DEC + d]; hn += q[2 * DEC + d];
    }
    float rr = 1.f / (1.f + expf(-(ir + hr)));
    float zz = 1.f / (1.f + expf(-(iz + hz)));
    float nn = tanhf(in_ + rr * hn);
    float hp = g_h[b * DEC + d];
    return (1.f - zz) * nn + zz * hp;
}

// ---------------- fused: gates(t-1) -> h_t, then Bahdanau attention(h_t) ----------------
// grid 16 blocks x 4 batch rows, 256 threads.
__global__ __launch_bounds__(256) void k_att(
    int t,
    const float* __restrict__ W_da, const float* __restrict__ b_da,
    const float* __restrict__ W_fa, const float* __restrict__ b_hh)
{
    __shared__ float sh_h [4][DEC];
    __shared__ float sh_a2[4][ATTD];
    __shared__ float sh_sc[4][64];
    const int tid = threadIdx.x;
    const int b0 = blockIdx.x << 2;

    if (t > 0) {
        #pragma unroll
        for (int ii = 0; ii < 8; ii++) {
            int idx = tid + (ii << 8);          // 0..2047
            int bi = idx >> 9, d = idx & 511;
            int b = b0 + bi;
            int r = (t - 1) * Bz + b;
            float hv = gru_update(r, b, d, b_hh);
            sh_h[bi][d] = hv;
            g_h[b * DEC + d] = hv;
            g_Hseq[(size_t)r * DEC + d] = hv;
        }
    } else {
        #pragma unroll
        for (int ii = 0; ii < 8; ii++) {
            int idx = tid + (ii << 8);
            sh_h[idx >> 9][idx & 511] = 0.f;
        }
    }
    __syncthreads();

    // att2[bi][j] = h[bi] @ W_da[:,j] + b_da[j]   (thread j handles all 4 bi)
    {
        int j = tid;
        float a0 = b_da[j], a1 = a0, a2 = a0, a3 = a0;
        #pragma unroll 8
        for (int k = 0; k < DEC; k++) {
            float w = W_da[k * ATTD + j];
            a0 += sh_h[0][k] * w;
            a1 += sh_h[1][k] * w;
            a2 += sh_h[2][k] * w;
            a3 += sh_h[3][k] * w;
        }
        sh_a2[0][j] = a0; sh_a2[1][j] = a1; sh_a2[2][j] = a2; sh_a2[3][j] = a3;
    }
    __syncthreads();

    // scores: warp per (bi,l) pair; lane sums 8 of the 256 ATT dims
    {
        int warp = tid >> 5, lane = tid & 31;
        float wfa[8];
        #pragma unroll
        for (int q = 0; q < 8; q++) wfa[q] = W_fa[lane + 32 * q];
        for (int p = warp; p < 4 * Lz; p += 8) {
            int bi = p / Lz, l = p % Lz;
            const float* arow = &g_att1[((size_t)(b0 + bi) * Lz + l) * ATTD];
            float s = 0.f;
            #pragma unroll
            for (int q = 0; q < 8; q++) {
                int j = lane + 32 * q;
                s += tanhf(arow[j] + sh_a2[bi][j]) * wfa[q];
            }
            #pragma unroll
            for (int o = 16; o; o >>= 1) s += __shfl_xor_sync(0xffffffffu, s, o);
            if (lane == 0) sh_sc[bi][l] = s;
        }
    }
    __syncthreads();

    // softmax over L=49 (b_fa shift is softmax-invariant)
    if (tid < 4) {
        float mx = -1e30f;
        for (int l = 0; l < Lz; l++) mx = fmaxf(mx, sh_sc[tid][l]);
        float sum = 0.f;
        for (int l = 0; l < Lz; l++) { float e = expf(sh_sc[tid][l] - mx); sh_sc[tid][l] = e; sum += e; }
        float inv = 1.f / sum;
        for (int l = 0; l < Lz; l++) sh_sc[tid][l] *= inv;
    }
    __syncthreads();

    // context[bi][d] = sum_l alpha[l] * enc[b,l,d]
    {
        int d = tid;  // handles d and d+256
        #pragma unroll
        for (int bi = 0; bi < 4; bi++) {
            const float* erow = &g_enc[(size_t)(b0 + bi) * Lz * DEC];
            float c0 = 0.f, c1 = 0.f;
            for (int l = 0; l < Lz; l++) {
                float al = sh_sc[bi][l];
                c0 += al * erow[l * DEC + d];
                c1 += al * erow[l * DEC + 256 + d];
            }
            g_ctx[(b0 + bi) * DEC + d]       = c0;
            g_ctx[(b0 + bi) * DEC + 256 + d] = c1;
        }
    }
}

// ---------------- final step's gate combine (t = T-1) ----------------
__global__ void k_gates(int t, const float* __restrict__ b_hh)
{
    int b = blockIdx.x, d = threadIdx.x;
    int r = t * Bz + b;
    float hv = gru_update(r, b, d, b_hh);
    g_h[b * DEC + d] = hv;
    g_Hseq[(size_t)r * DEC + d] = hv;
}

// ---------------- launcher ----------------
extern "C" void kernel_launch(void* const* d_in, const int* in_sizes, int n_in,
                              void* d_out, int out_size)
{
    (void)in_sizes; (void)n_in; (void)out_size;
    const float* spatial = (const float*)d_in[0];
    const int*   cap     = (const int*)  d_in[1];
    const float* W_feat  = (const float*)d_in[2];
    const float* b_feat  = (const float*)d_in[3];
    const float* W_ea    = (const float*)d_in[4];
    const float* b_ea    = (const float*)d_in[5];
    const float* W_da    = (const float*)d_in[6];
    const float* b_da    = (const float*)d_in[7];
    const float* W_fa    = (const float*)d_in[8];
    /* b_fa (d_in[9]) is softmax-invariant */
    const float* emb     = (const float*)d_in[10];
    const float* W_ih    = (const float*)d_in[11];
    const float* W_hh    = (const float*)d_in[12];
    const float* b_ih    = (const float*)d_in[13];
    const float* b_hh    = (const float*)d_in[14];
    const float* W_fc    = (const float*)d_in[15];
    const float* b_fc    = (const float*)d_in[16];
    float* out = (float*)d_out;

    float *p_enc, *p_att1, *p_xemb, *p_gie, *p_wihe, *p_hseq;
    cudaGetSymbolAddress((void**)&p_enc,  g_enc);
    cudaGetSymbolAddress((void**)&p_att1, g_att1);
    cudaGetSymbolAddress((void**)&p_xemb, g_Xemb);
    cudaGetSymbolAddress((void**)&p_gie,  g_gie);
    cudaGetSymbolAddress((void**)&p_wihe, g_Wihe);
    cudaGetSymbolAddress((void**)&p_hseq, g_Hseq);

    // setup
    k_init<<<Tz * Bz, EMBD>>>(cap, emb);                       // zero h + gather emb
    k_transpose<<<(DEC * H3 + 255) / 256, 256>>>(W_ih, W_hh);

    // big loop-invariant GEMMs
    k_gemm<<<dim3(4, 25), 256>>>(spatial, W_feat, b_feat, p_enc, Bz * Lz, DEC, ENCD, 0);
    k_gemm<<<dim3(2, 25), 256>>>(p_enc, W_ea, b_ea, p_att1, Bz * Lz, ATTD, DEC, 0);
    k_gemm<<<dim3(12, 25), 256>>>(p_xemb, p_wihe, b_ih, p_gie, Tz * Bz, H3, DEC, 0);

    // sequential decode: 2 nodes per step
    for (int t = 0; t < Tz; t++) {
        k_att<<<16, 256>>>(t, W_da, b_da, W_fa, b_hh);
        k_stepgemm<<<dim3(24, 4, 2), 256>>>();
    }
    k_gates<<<Bz, DEC>>>(Tz - 1, b_hh);                        // finalize h_{T-1} -> Hseq

    // one big fc GEMM over all timesteps, writes [B,T,V] directly
    k_gemm<<<dim3((VOC + 127) / 128, 25), 256>>>(p_hseq, W_fc, b_fc, out, Tz * Bz, VOC, DEC, 1);
}

// round 6
// speedup vs baseline: 1.0020x; 1.0020x over previous
#include <cuda_runtime.h>
#include <math.h>

#define Bz   64
#define Lz   49
#define ENCD 2048
#define DEC  512
#define ATTD 256
#define VOC  10000
#define Tz   50
#define H3   1536
#define EMBD 512

// ---------------- scratch (device globals; no runtime alloc) ----------------
__device__ float g_enc [Bz*Lz*DEC];     // [B,L,DEC]
__device__ float g_att1[Bz*Lz*ATTD];    // [B,L,ATT]
__device__ float g_Xemb[Tz*Bz*EMBD];    // gathered embeddings, row r = t*B+b
__device__ float g_gie [Tz*Bz*H3];      // emb part of GRU input gates (+b_ih)
__device__ float g_Wihe[DEC*H3];        // W_ih[:, :512]  transposed -> [k][j]
__device__ float g_Wihc[DEC*H3];        // W_ih[:, 512:]  transposed -> [k][j]
__device__ float g_Whh [DEC*H3];        // W_hh transposed -> [k][j]
__device__ float g_h   [Bz*DEC];        // current hidden
__device__ float g_ctx [Bz*DEC];        // attention context
__device__ float g_part[8*Bz*H3];       // split-K partials: [mat(2)*4+split][b][j]
__device__ float g_Hseq[Tz*Bz*DEC];     // h_new per step, row r = t*B+b

// ---------------- init: zero h + gather embeddings ----------------
__global__ void k_init(const int* __restrict__ cap, const float* __restrict__ emb)
{
    int i = blockIdx.x * blockDim.x + threadIdx.x;   // launched with exactly T*B*EMB threads
    if (i < Bz * DEC) g_h[i] = 0.f;
    int d = i & 511;
    int r = i >> 9;            // t*B + b
    int t = r >> 6;
    int b = r & 63;
    int tok = cap[b * Tz + t];
    g_Xemb[i] = emb[(size_t)tok * EMBD + d];
}

// ---------------- one-time weight transposes ----------------
__global__ void k_transpose(const float* __restrict__ W_ih, const float* __restrict__ W_hh)
{
    int i = blockIdx.x * blockDim.x + threadIdx.x;   // over DEC*H3
    if (i >= DEC * H3) return;
    int j = i >> 9;       // 0..1535 (row of torch weight)
    int k = i & 511;      // 0..511
    g_Wihe[k * H3 + j] = W_ih[j * (EMBD + DEC) + k];
    g_Wihc[k * H3 + j] = W_ih[j * (EMBD + DEC) + EMBD + k];
    g_Whh [k * H3 + j] = W_hh[j * DEC + k];
}

// ---------------- generic fp32 GEMM: C[M,N] = A[M,K] @ B[K,N] + bias ----------------
// 128x128 block tile, 8x8 microtile, 256 threads. remap=1 writes fc output as
// out[(b*T + t)*V + n] with row = t*B + b.
__global__ __launch_bounds__(256) void k_gemm(
    const float* __restrict__ A, const float* __restrict__ Bm,
    const float* __restrict__ bias, float* __restrict__ C,
    int M, int N, int K, int remap)
{
    __shared__ float sA[16][132];
    __shared__ float sB[16][128];
    const int tid = threadIdx.x;
    const int tx = tid & 15, ty = tid >> 4;
    const int mb = blockIdx.y << 7;
    const int nb = blockIdx.x << 7;
    float acc[8][8] = {};

    for (int k0 = 0; k0 < K; k0 += 16) {
        #pragma unroll
        for (int u = 0; u < 2; u++) {
            int f = tid + u * 256;
            // A tile: 128 rows x 16 k  (512 float4)
            int arow = f >> 2, akq = (f & 3) << 2;
            float4 av = make_float4(0.f, 0.f, 0.f, 0.f);
            if (mb + arow < M)
                av = *reinterpret_cast<const float4*>(&A[(size_t)(mb + arow) * K + k0 + akq]);
            sA[akq + 0][arow] = av.x; sA[akq + 1][arow] = av.y;
            sA[akq + 2][arow] = av.z; sA[akq + 3][arow] = av.w;
            // B tile: 16 rows x 128 cols (512 float4), guard N
            int brow = f >> 5, bcol = (f & 31) << 2;
            int n = nb + bcol;
            const float* bp = &Bm[(size_t)(k0 + brow) * N + n];
            float4 bv;
            if (n + 3 < N) bv = *reinterpret_cast<const float4*>(bp);
            else {
                bv.x = (n + 0 < N) ? bp[0] : 0.f;
                bv.y = (n + 1 < N) ? bp[1] : 0.f;
                bv.z = (n + 2 < N) ? bp[2] : 0.f;
                bv.w = (n + 3 < N) ? bp[3] : 0.f;
            }
            *reinterpret_cast<float4*>(&sB[brow][bcol]) = bv;
        }
        __syncthreads();
        #pragma unroll
        for (int kk = 0; kk < 16; kk++) {
            float4 a0 = *reinterpret_cast<const float4*>(&sA[kk][ty * 8]);
            float4 a1 = *reinterpret_cast<const float4*>(&sA[kk][ty * 8 + 4]);
            float4 b0 = *reinterpret_cast<const float4*>(&sB[kk][tx * 8]);
            float4 b1 = *reinterpret_cast<const float4*>(&sB[kk][tx * 8 + 4]);
            float av[8] = {a0.x, a0.y, a0.z, a0.w, a1.x, a1.y, a1.z, a1.w};
            float bv[8] = {b0.x, b0.y, b0.z, b0.w, b1.x, b1.y, b1.z, b1.w};
            #pragma unroll
            for (int i = 0; i < 8; i++)
                #pragma unroll
                for (int j = 0; j < 8; j++)
                    acc[i][j] += av[i] * bv[j];
        }
        __syncthreads();
    }

    #pragma unroll
    for (int i = 0; i < 8; i++) {
        int row = mb + ty * 8 + i;
        if (row >= M) break;
        #pragma unroll
        for (int j = 0; j < 8; j++) {
            int col = nb + tx * 8 + j;
            if (col < N) {
                float v = acc[i][j] + bias[col];
                if (remap) {
                    int t = row >> 6, bb = row & 63;
                    C[((size_t)(bb * Tz + t)) * VOC + col] = v;
                } else {
                    C[(size_t)row * N + col] = v;
                }
            }
        }
    }
}

// ---------------- per-step dual GEMM (gi_c and gh), split-K=4 ----------------
// grid (24 n-tiles, 4 k-splits, 2 mats), block 256. Each block: 64x64x128.
__global__ __launch_bounds__(256) void k_stepgemm()
{
    __shared__ float sA[16][68];
    __shared__ float sB[16][64];
    const int tid = threadIdx.x;
    const int tx = tid & 15, ty = tid >> 4;
    const int nb = blockIdx.x << 6;
    const int kbase = blockIdx.y << 7;
    const int z = blockIdx.z;
    const float* A  = z ? g_h   : g_ctx;
    const float* Bw = z ? g_Whh : g_Wihc;
    float* out = &g_part[(size_t)((z * 4 + blockIdx.y) * Bz) * H3];
    float acc[4][4] = {};
    const int arow = tid >> 2, akq = (tid & 3) << 2;
    const int brow = tid >> 4, bcol = (tid & 15) << 2;

    for (int kc = 0; kc < 128; kc += 16) {
        int k0 = kbase + kc;
        float4 av = *reinterpret_cast<const float4*>(&A[arow * DEC + k0 + akq]);
        sA[akq + 0][arow] = av.x; sA[akq + 1][arow] = av.y;
        sA[akq + 2][arow] = av.z; sA[akq + 3][arow] = av.w;
        float4 bv = *reinterpret_cast<const float4*>(&Bw[(size_t)(k0 + brow) * H3 + nb + bcol]);
        *reinterpret_cast<float4*>(&sB[brow][bcol]) = bv;
        __syncthreads();
        #pragma unroll
        for (int kk = 0; kk < 16; kk++) {
            float4 a = *reinterpret_cast<const float4*>(&sA[kk][ty * 4]);
            float4 b = *reinterpret_cast<const float4*>(&sB[kk][tx * 4]);
            float avr[4] = {a.x, a.y, a.z, a.w};
            float bvr[4] = {b.x, b.y, b.z, b.w};
            #pragma unroll
            for (int i = 0; i < 4; i++)
                #pragma unroll
                for (int j = 0; j < 4; j++)
                    acc[i][j] += avr[i] * bvr[j];
        }
        __syncthreads();
    }
    #pragma unroll
    for (int i = 0; i < 4; i++)
        #pragma unroll
        for (int j = 0; j < 4; j++)
            out[(size_t)(ty * 4 + i) * H3 + nb + tx * 4 + j] = acc[i][j];
}

// ---------------- GRU gate combine (reads split-K partials) ----------------
__device__ __forceinline__ float gru_update(int r, int b, int d, const float* __restrict__ b_hh)
{
    const float* gie = &g_gie[(size_t)r * H3];
    float ir = gie[d], iz = gie[DEC + d], in_ = gie[2 * DEC + d];
    float hr = b_hh[d], hz = b_hh[DEC + d], hn = b_hh[2 * DEC + d];
    #pragma unroll
    for (int s = 0; s < 4; s++) {
        const float* p = &g_part[(size_t)(s * Bz + b) * H3];
        ir += p[d]; iz += p[DEC + d]; in_ += p[2 * DEC + d];
        const float* q = &g_part[(size_t)((4 + s) * Bz + b) * H3];
        hr += q[d]; hz += q[DEC + d]; hn += q[2 * DEC + d];
    }
    float rr = 1.f / (1.f + expf(-(ir + hr)));
    float zz = 1.f / (1.f + expf(-(iz + hz)));
    float nn = tanhf(in_ + rr * hn);
    float hp = g_h[b * DEC + d];
    return (1.f - zz) * nn + zz * hp;
}

// ---------------- fused: gates(t-1) -> h_t, then Bahdanau attention(h_t) ----------------
// grid 16 blocks x 4 batch rows, 256 threads.
__global__ __launch_bounds__(256) void k_att(
    int t,
    const float* __restrict__ W_da, const float* __restrict__ b_da,
    const float* __restrict__ W_fa, const float* __restrict__ b_hh)
{
    __shared__ float sh_h [4][DEC];
    __shared__ float sh_a2[4][ATTD];
    __shared__ float sh_sc[4][64];
    const int tid = threadIdx.x;
    const int b0 = blockIdx.x << 2;

    if (t > 0) {
        #pragma unroll
        for (int ii = 0; ii < 8; ii++) {
            int idx = tid + (ii << 8);          // 0..2047
            int bi = idx >> 9, d = idx & 511;
            int b = b0 + bi;
            int r = (t - 1) * Bz + b;
            float hv = gru_update(r, b, d, b_hh);
            sh_h[bi][d] = hv;
            g_h[b * DEC + d] = hv;
            g_Hseq[(size_t)r * DEC + d] = hv;
        }
    } else {
        #pragma unroll
        for (int ii = 0; ii < 8; ii++) {
            int idx = tid + (ii << 8);
            sh_h[idx >> 9][idx & 511] = 0.f;
        }
    }
    __syncthreads();

    // att2[bi][j] = h[bi] @ W_da[:,j] + b_da[j]   (thread j handles all 4 bi)
    {
        int j = tid;
        float a0 = b_da[j], a1 = a0, a2 = a0, a3 = a0;
        #pragma unroll 8
        for (int k = 0; k < DEC; k++) {
            float w = W_da[k * ATTD + j];
            a0 += sh_h[0][k] * w;
            a1 += sh_h[1][k] * w;
            a2 += sh_h[2][k] * w;
            a3 += sh_h[3][k] * w;
        }
        sh_a2[0][j] = a0; sh_a2[1][j] = a1; sh_a2[2][j] = a2; sh_a2[3][j] = a3;
    }
    __syncthreads();

    // scores: warp per (bi,l) pair; lane sums 8 of the 256 ATT dims
    {
        int warp = tid >> 5, lane = tid & 31;
        float wfa[8];
        #pragma unroll
        for (int q = 0; q < 8; q++) wfa[q] = W_fa[lane + 32 * q];
        for (int p = warp; p < 4 * Lz; p += 8) {
            int bi = p / Lz, l = p % Lz;
            const float* arow = &g_att1[((size_t)(b0 + bi) * Lz + l) * ATTD];
            float s = 0.f;
            #pragma unroll
            for (int q = 0; q < 8; q++) {
                int j = lane + 32 * q;
                s += tanhf(arow[j] + sh_a2[bi][j]) * wfa[q];
            }
            #pragma unroll
            for (int o = 16; o; o >>= 1) s += __shfl_xor_sync(0xffffffffu, s, o);
            if (lane == 0) sh_sc[bi][l] = s;
        }
    }
    __syncthreads();

    // softmax over L=49 (b_fa shift is softmax-invariant)
    if (tid < 4) {
        float mx = -1e30f;
        for (int l = 0; l < Lz; l++) mx = fmaxf(mx, sh_sc[tid][l]);
        float sum = 0.f;
        for (int l = 0; l < Lz; l++) { float e = expf(sh_sc[tid][l] - mx); sh_sc[tid][l] = e; sum += e; }
        float inv = 1.f / sum;
        for (int l = 0; l < Lz; l++) sh_sc[tid][l] *= inv;
    }
    __syncthreads();

    // context[bi][d] = sum_l alpha[l] * enc[b,l,d]
    {
        int d = tid;  // handles d and d+256
        #pragma unroll
        for (int bi = 0; bi < 4; bi++) {
            const float* erow = &g_enc[(size_t)(b0 + bi) * Lz * DEC];
            float c0 = 0.f, c1 = 0.f;
            for (int l = 0; l < Lz; l++) {
                float al = sh_sc[bi][l];
                c0 += al * erow[l * DEC + d];
                c1 += al * erow[l * DEC + 256 + d];
            }
            g_ctx[(b0 + bi) * DEC + d]       = c0;
            g_ctx[(b0 + bi) * DEC + 256 + d] = c1;
        }
    }
}

// ---------------- final step's gate combine (t = T-1) ----------------
__global__ void k_gates(int t, const float* __restrict__ b_hh)
{
    int b = blockIdx.x, d = threadIdx.x;
    int r = t * Bz + b;
    float hv = gru_update(r, b, d, b_hh);
    g_h[b * DEC + d] = hv;
    g_Hseq[(size_t)r * DEC + d] = hv;
}

// ---------------- launcher ----------------
extern "C" void kernel_launch(void* const* d_in, const int* in_sizes, int n_in,
                              void* d_out, int out_size)
{
    (void)in_sizes; (void)n_in; (void)out_size;
    const float* spatial = (const float*)d_in[0];
    const int*   cap     = (const int*)  d_in[1];
    const float* W_feat  = (const float*)d_in[2];
    const float* b_feat  = (const float*)d_in[3];
    const float* W_ea    = (const float*)d_in[4];
    const float* b_ea    = (const float*)d_in[5];
    const float* W_da    = (const float*)d_in[6];
    const float* b_da    = (const float*)d_in[7];
    const float* W_fa    = (const float*)d_in[8];
    /* b_fa (d_in[9]) is softmax-invariant */
    const float* emb     = (const float*)d_in[10];
    const float* W_ih    = (const float*)d_in[11];
    const float* W_hh    = (const float*)d_in[12];
    const float* b_ih    = (const float*)d_in[13];
    const float* b_hh    = (const float*)d_in[14];
    const float* W_fc    = (const float*)d_in[15];
    const float* b_fc    = (const float*)d_in[16];
    float* out = (float*)d_out;

    float *p_enc, *p_att1, *p_xemb, *p_gie, *p_wihe, *p_hseq;
    cudaGetSymbolAddress((void**)&p_enc,  g_enc);
    cudaGetSymbolAddress((void**)&p_att1, g_att1);
    cudaGetSymbolAddress((void**)&p_xemb, g_Xemb);
    cudaGetSymbolAddress((void**)&p_gie,  g_gie);
    cudaGetSymbolAddress((void**)&p_wihe, g_Wihe);
    cudaGetSymbolAddress((void**)&p_hseq, g_Hseq);

    // setup
    k_init<<<Tz * Bz, EMBD>>>(cap, emb);                       // zero h + gather emb
    k_transpose<<<(DEC * H3 + 255) / 256, 256>>>(W_ih, W_hh);

    // big loop-invariant GEMMs
    k_gemm<<<dim3(4, 25), 256>>>(spatial, W_feat, b_feat, p_enc, Bz * Lz, DEC, ENCD, 0);
    k_gemm<<<dim3(2, 25), 256>>>(p_enc, W_ea, b_ea, p_att1, Bz * Lz, ATTD, DEC, 0);
    k_gemm<<<dim3(12, 25), 256>>>(p_xemb, p_wihe, b_ih, p_gie, Tz * Bz, H3, DEC, 0);

    // sequential decode: 2 nodes per step
    for (int t = 0; t < Tz; t++) {
        k_att<<<16, 256>>>(t, W_da, b_da, W_fa, b_hh);
        k_stepgemm<<<dim3(24, 4, 2), 256>>>();
    }
    k_gates<<<Bz, DEC>>>(Tz - 1, b_hh);                        // finalize h_{T-1} -> Hseq

    // one big fc GEMM over all timesteps, writes [B,T,V] directly
    k_gemm<<<dim3((VOC + 127) / 128, 25), 256>>>(p_hseq, W_fc, b_fc, out, Tz * Bz, VOC, DEC, 1);
}

// round 7
// speedup vs baseline: 1.0233x; 1.0212x over previous
#include <cuda_runtime.h>
#include <math.h>

#define Bz   64
#define Lz   49
#define ENCD 2048
#define DEC  512
#define ATTD 256
#define VOC  10000
#define Tz   50
#define H3   1536
#define EMBD 512

// ---------------- scratch (device globals; no runtime alloc) ----------------
__device__ float g_enc [Bz*Lz*DEC];     // [B,L,DEC]
__device__ float g_att1[Bz*Lz*ATTD];    // [B,L,ATT]
__device__ float g_Xemb[Tz*Bz*EMBD];    // gathered embeddings, row r = t*B+b
__device__ float g_gie [Tz*Bz*H3];      // emb part of GRU input gates (+b_ih)
__device__ float g_Wihe[DEC*H3];        // W_ih[:, :512]  transposed -> [k][j]
__device__ float g_Wihc[DEC*H3];        // W_ih[:, 512:]  transposed -> [k][j]
__device__ float g_Whh [DEC*H3];        // W_hh transposed -> [k][j]
__device__ float g_h   [Bz*DEC];        // current hidden
__device__ float g_ctx [Bz*DEC];        // attention context
__device__ float g_part[8*Bz*H3];       // split-K partials: [mat(2)*4+split][b][j]
__device__ float g_Hseq[Tz*Bz*DEC];     // h_new per step, row r = t*B+b

// ---------------- init: zero h + gather embeddings ----------------
__global__ void k_init(const int* __restrict__ cap, const float* __restrict__ emb)
{
    int i = blockIdx.x * blockDim.x + threadIdx.x;   // launched with exactly T*B*EMB threads
    if (i < Bz * DEC) g_h[i] = 0.f;
    int d = i & 511;
    int r = i >> 9;            // t*B + b
    int t = r >> 6;
    int b = r & 63;
    int tok = cap[b * Tz + t];
    g_Xemb[i] = emb[(size_t)tok * EMBD + d];
}

// ---------------- one-time weight transposes ----------------
__global__ void k_transpose(const float* __restrict__ W_ih, const float* __restrict__ W_hh)
{
    int i = blockIdx.x * blockDim.x + threadIdx.x;   // over DEC*H3
    if (i >= DEC * H3) return;
    int j = i >> 9;       // 0..1535 (row of torch weight)
    int k = i & 511;      // 0..511
    g_Wihe[k * H3 + j] = W_ih[j * (EMBD + DEC) + k];
    g_Wihc[k * H3 + j] = W_ih[j * (EMBD + DEC) + EMBD + k];
    g_Whh [k * H3 + j] = W_hh[j * DEC + k];
}

// ---------------- generic fp32 GEMM: C[M,N] = A[M,K] @ B[K,N] + bias ----------------
// 128x128 block tile, 8x8 microtile, 256 threads. remap=1 writes fc output as
// out[(b*T + t)*V + n] with row = t*B + b.
__global__ __launch_bounds__(256) void k_gemm(
    const float* __restrict__ A, const float* __restrict__ Bm,
    const float* __restrict__ bias, float* __restrict__ C,
    int M, int N, int K, int remap)
{
    __shared__ float sA[16][132];
    __shared__ float sB[16][128];
    const int tid = threadIdx.x;
    const int tx = tid & 15, ty = tid >> 4;
    const int mb = blockIdx.y << 7;
    const int nb = blockIdx.x << 7;
    float acc[8][8] = {};

    for (int k0 = 0; k0 < K; k0 += 16) {
        #pragma unroll
        for (int u = 0; u < 2; u++) {
            int f = tid + u * 256;
            // A tile: 128 rows x 16 k  (512 float4)
            int arow = f >> 2, akq = (f & 3) << 2;
            float4 av = make_float4(0.f, 0.f, 0.f, 0.f);
            if (mb + arow < M)
                av = *reinterpret_cast<const float4*>(&A[(size_t)(mb + arow) * K + k0 + akq]);
            sA[akq + 0][arow] = av.x; sA[akq + 1][arow] = av.y;
            sA[akq + 2][arow] = av.z; sA[akq + 3][arow] = av.w;
            // B tile: 16 rows x 128 cols (512 float4), guard N
            int brow = f >> 5, bcol = (f & 31) << 2;
            int n = nb + bcol;
            const float* bp = &Bm[(size_t)(k0 + brow) * N + n];
            float4 bv;
            if (n + 3 < N) bv = *reinterpret_cast<const float4*>(bp);
            else {
                bv.x = (n + 0 < N) ? bp[0] : 0.f;
                bv.y = (n + 1 < N) ? bp[1] : 0.f;
                bv.z = (n + 2 < N) ? bp[2] : 0.f;
                bv.w = (n + 3 < N) ? bp[3] : 0.f;
            }
            *reinterpret_cast<float4*>(&sB[brow][bcol]) = bv;
        }
        __syncthreads();
        #pragma unroll
        for (int kk = 0; kk < 16; kk++) {
            float4 a0 = *reinterpret_cast<const float4*>(&sA[kk][ty * 8]);
            float4 a1 = *reinterpret_cast<const float4*>(&sA[kk][ty * 8 + 4]);
            float4 b0 = *reinterpret_cast<const float4*>(&sB[kk][tx * 8]);
            float4 b1 = *reinterpret_cast<const float4*>(&sB[kk][tx * 8 + 4]);
            float av[8] = {a0.x, a0.y, a0.z, a0.w, a1.x, a1.y, a1.z, a1.w};
            float bv[8] = {b0.x, b0.y, b0.z, b0.w, b1.x, b1.y, b1.z, b1.w};
            #pragma unroll
            for (int i = 0; i < 8; i++)
                #pragma unroll
                for (int j = 0; j < 8; j++)
                    acc[i][j] += av[i] * bv[j];
        }
        __syncthreads();
    }

    #pragma unroll
    for (int i = 0; i < 8; i++) {
        int row = mb + ty * 8 + i;
        if (row >= M) break;
        #pragma unroll
        for (int j = 0; j < 8; j++) {
            int col = nb + tx * 8 + j;
            if (col < N) {
                float v = acc[i][j] + bias[col];
                if (remap) {
                    int t = row >> 6, bb = row & 63;
                    C[((size_t)(bb * Tz + t)) * VOC + col] = v;
                } else {
                    C[(size_t)row * N + col] = v;
                }
            }
        }
    }
}

// ---------------- per-step dual GEMM (gi_c and gh), split-K=4 ----------------
// grid (24 n-tiles, 4 k-splits, 2 mats), block 256. Each block: 64x64x128.
__global__ __launch_bounds__(256) void k_stepgemm()
{
    __shared__ float sA[16][68];
    __shared__ float sB[16][64];
    const int tid = threadIdx.x;
    const int tx = tid & 15, ty = tid >> 4;
    const int nb = blockIdx.x << 6;
    const int kbase = blockIdx.y << 7;
    const int z = blockIdx.z;
    const float* A  = z ? g_h   : g_ctx;
    const float* Bw = z ? g_Whh : g_Wihc;
    float* out = &g_part[(size_t)((z * 4 + blockIdx.y) * Bz) * H3];
    float acc[4][4] = {};
    const int arow = tid >> 2, akq = (tid & 3) << 2;
    const int brow = tid >> 4, bcol = (tid & 15) << 2;

    for (int kc = 0; kc < 128; kc += 16) {
        int k0 = kbase + kc;
        float4 av = *reinterpret_cast<const float4*>(&A[arow * DEC + k0 + akq]);
        sA[akq + 0][arow] = av.x; sA[akq + 1][arow] = av.y;
        sA[akq + 2][arow] = av.z; sA[akq + 3][arow] = av.w;
        float4 bv = *reinterpret_cast<const float4*>(&Bw[(size_t)(k0 + brow) * H3 + nb + bcol]);
        *reinterpret_cast<float4*>(&sB[brow][bcol]) = bv;
        __syncthreads();
        #pragma unroll
        for (int kk = 0; kk < 16; kk++) {
            float4 a = *reinterpret_cast<const float4*>(&sA[kk][ty * 4]);
            float4 b = *reinterpret_cast<const float4*>(&sB[kk][tx * 4]);
            float avr[4] = {a.x, a.y, a.z, a.w};
            float bvr[4] = {b.x, b.y, b.z, b.w};
            #pragma unroll
            for (int i = 0; i < 4; i++)
                #pragma unroll
                for (int j = 0; j < 4; j++)
                    acc[i][j] += avr[i] * bvr[j];
        }
        __syncthreads();
    }
    #pragma unroll
    for (int i = 0; i < 4; i++)
        #pragma unroll
        for (int j = 0; j < 4; j++)
            out[(size_t)(ty * 4 + i) * H3 + nb + tx * 4 + j] = acc[i][j];
}

// ---------------- GRU gate combine (reads split-K partials) ----------------
__device__ __forceinline__ float gru_update(int r, int b, int d, const float* __restrict__ b_hh)
{
    const float* gie = &g_gie[(size_t)r * H3];
    float ir = gie[d], iz = gie[DEC + d], in_ = gie[2 * DEC + d];
    float hr = b_hh[d], hz = b_hh[DEC + d], hn = b_hh[2 * DEC + d];
    #pragma unroll
    for (int s = 0; s < 4; s++) {
        const float* p = &g_part[(size_t)(s * Bz + b) * H3];
        ir += p[d]; iz += p[DEC + d]; in_ += p[2 * DEC + d];
        const float* q = &g_part[(size_t)((4 + s) * Bz + b) * H3];
        hr += q[d]; hz += q[DEC + d]; hn += q[2 * DEC + d];
    }
    float rr = 1.f / (1.f + expf(-(ir + hr)));
    float zz = 1.f / (1.f + expf(-(iz + hz)));
    float nn = tanhf(in_ + rr * hn);
    float hp = g_h[b * DEC + d];
    return (1.f - zz) * nn + zz * hp;
}

// ---------------- fused: gates(t-1) -> h_t, then Bahdanau attention(h_t) ----------------
// grid 16 blocks x 4 batch rows, 256 threads.
__global__ __launch_bounds__(256) void k_att(
    int t,
    const float* __restrict__ W_da, const float* __restrict__ b_da,
    const float* __restrict__ W_fa, const float* __restrict__ b_hh)
{
    __shared__ float sh_h [4][DEC];
    __shared__ float sh_a2[4][ATTD];
    __shared__ float sh_sc[4][64];
    const int tid = threadIdx.x;
    const int b0 = blockIdx.x << 2;

    if (t > 0) {
        #pragma unroll
        for (int ii = 0; ii < 8; ii++) {
            int idx = tid + (ii << 8);          // 0..2047
            int bi = idx >> 9, d = idx & 511;
            int b = b0 + bi;
            int r = (t - 1) * Bz + b;
            float hv = gru_update(r, b, d, b_hh);
            sh_h[bi][d] = hv;
            g_h[b * DEC + d] = hv;
            g_Hseq[(size_t)r * DEC + d] = hv;
        }
    } else {
        #pragma unroll
        for (int ii = 0; ii < 8; ii++) {
            int idx = tid + (ii << 8);
            sh_h[idx >> 9][idx & 511] = 0.f;
        }
    }
    __syncthreads();

    // att2[bi][j] = h[bi] @ W_da[:,j] + b_da[j]   (thread j handles all 4 bi)
    {
        int j = tid;
        float a0 = b_da[j], a1 = a0, a2 = a0, a3 = a0;
        #pragma unroll 8
        for (int k = 0; k < DEC; k++) {
            float w = W_da[k * ATTD + j];
            a0 += sh_h[0][k] * w;
            a1 += sh_h[1][k] * w;
            a2 += sh_h[2][k] * w;
            a3 += sh_h[3][k] * w;
        }
        sh_a2[0][j] = a0; sh_a2[1][j] = a1; sh_a2[2][j] = a2; sh_a2[3][j] = a3;
    }
    __syncthreads();

    // scores: warp per (bi,l) pair; lane sums 8 of the 256 ATT dims
    {
        int warp = tid >> 5, lane = tid & 31;
        float wfa[8];
        #pragma unroll
        for (int q = 0; q < 8; q++) wfa[q] = W_fa[lane + 32 * q];
        for (int p = warp; p < 4 * Lz; p += 8) {
            int bi = p / Lz, l = p % Lz;
            const float* arow = &g_att1[((size_t)(b0 + bi) * Lz + l) * ATTD];
            float s = 0.f;
            #pragma unroll
            for (int q = 0; q < 8; q++) {
                int j = lane + 32 * q;
                s += tanhf(arow[j] + sh_a2[bi][j]) * wfa[q];
            }
            #pragma unroll
            for (int o = 16; o; o >>= 1) s += __shfl_xor_sync(0xffffffffu, s, o);
            if (lane == 0) sh_sc[bi][l] = s;
        }
    }
    __syncthreads();

    // softmax over L=49 (b_fa shift is softmax-invariant)
    if (tid < 4) {
        float mx = -1e30f;
        for (int l = 0; l < Lz; l++) mx = fmaxf(mx, sh_sc[tid][l]);
        float sum = 0.f;
        for (int l = 0; l < Lz; l++) { float e = expf(sh_sc[tid][l] - mx); sh_sc[tid][l] = e; sum += e; }
        float inv = 1.f / sum;
        for (int l = 0; l < Lz; l++) sh_sc[tid][l] *= inv;
    }
    __syncthreads();

    // context[bi][d] = sum_l alpha[l] * enc[b,l,d]
    {
        int d = tid;  // handles d and d+256
        #pragma unroll
        for (int bi = 0; bi < 4; bi++) {
            const float* erow = &g_enc[(size_t)(b0 + bi) * Lz * DEC];
            float c0 = 0.f, c1 = 0.f;
            for (int l = 0; l < Lz; l++) {
                float al = sh_sc[bi][l];
                c0 += al * erow[l * DEC + d];
                c1 += al * erow[l * DEC + 256 + d];
            }
            g_ctx[(b0 + bi) * DEC + d]       = c0;
            g_ctx[(b0 + bi) * DEC + 256 + d] = c1;
        }
    }
}

// ---------------- final step's gate combine (t = T-1) ----------------
__global__ void k_gates(int t, const float* __restrict__ b_hh)
{
    int b = blockIdx.x, d = threadIdx.x;
    int r = t * Bz + b;
    float hv = gru_update(r, b, d, b_hh);
    g_h[b * DEC + d] = hv;
    g_Hseq[(size_t)r * DEC + d] = hv;
}

// ---------------- launcher ----------------
extern "C" void kernel_launch(void* const* d_in, const int* in_sizes, int n_in,
                              void* d_out, int out_size)
{
    (void)in_sizes; (void)n_in; (void)out_size;
    const float* spatial = (const float*)d_in[0];
    const int*   cap     = (const int*)  d_in[1];
    const float* W_feat  = (const float*)d_in[2];
    const float* b_feat  = (const float*)d_in[3];
    const float* W_ea    = (const float*)d_in[4];
    const float* b_ea    = (const float*)d_in[5];
    const float* W_da    = (const float*)d_in[6];
    const float* b_da    = (const float*)d_in[7];
    const float* W_fa    = (const float*)d_in[8];
    /* b_fa (d_in[9]) is softmax-invariant */
    const float* emb     = (const float*)d_in[10];
    const float* W_ih    = (const float*)d_in[11];
    const float* W_hh    = (const float*)d_in[12];
    const float* b_ih    = (const float*)d_in[13];
    const float* b_hh    = (const float*)d_in[14];
    const float* W_fc    = (const float*)d_in[15];
    const float* b_fc    = (const float*)d_in[16];
    float* out = (float*)d_out;

    float *p_enc, *p_att1, *p_xemb, *p_gie, *p_wihe, *p_hseq;
    cudaGetSymbolAddress((void**)&p_enc,  g_enc);
    cudaGetSymbolAddress((void**)&p_att1, g_att1);
    cudaGetSymbolAddress((void**)&p_xemb, g_Xemb);
    cudaGetSymbolAddress((void**)&p_gie,  g_gie);
    cudaGetSymbolAddress((void**)&p_wihe, g_Wihe);
    cudaGetSymbolAddress((void**)&p_hseq, g_Hseq);

    // setup
    k_init<<<Tz * Bz, EMBD>>>(cap, emb);                       // zero h + gather emb
    k_transpose<<<(DEC * H3 + 255) / 256, 256>>>(W_ih, W_hh);

    // big loop-invariant GEMMs
    k_gemm<<<dim3(4, 25), 256>>>(spatial, W_feat, b_feat, p_enc, Bz * Lz, DEC, ENCD, 0);
    k_gemm<<<dim3(2, 25), 256>>>(p_enc, W_ea, b_ea, p_att1, Bz * Lz, ATTD, DEC, 0);
    k_gemm<<<dim3(12, 25), 256>>>(p_xemb, p_wihe, b_ih, p_gie, Tz * Bz, H3, DEC, 0);

    // sequential decode: 2 nodes per step
    for (int t = 0; t < Tz; t++) {
        k_att<<<16, 256>>>(t, W_da, b_da, W_fa, b_hh);
        k_stepgemm<<<dim3(24, 4, 2), 256>>>();
    }
    k_gates<<<Bz, DEC>>>(Tz - 1, b_hh);                        // finalize h_{T-1} -> Hseq

    // one big fc GEMM over all timesteps, writes [B,T,V] directly
    k_gemm<<<dim3((VOC + 127) / 128, 25), 256>>>(p_hseq, W_fc, b_fc, out, Tz * Bz, VOC, DEC, 1);
}

// round 9
// speedup vs baseline: 1.7904x; 1.7496x over previous
#include <cuda_runtime.h>
#include <cuda_bf16.h>
#include <math.h>
#include <stdint.h>

#define Bz   64
#define Lz   49
#define ENCD 2048
#define DEC  512
#define ATTD 256
#define VOC  10000
#define Tz   50
#define H3   1536
#define EMBD 512

typedef __nv_bfloat16 bf16;

// ---------------- scratch (device globals; no runtime alloc) ----------------
__device__ float g_enc [Bz*Lz*DEC];     // [B,L,DEC]
__device__ float g_att1[Bz*Lz*ATTD];    // [B,L,ATT]
__device__ float g_Xemb[Tz*Bz*EMBD];    // gathered embeddings, row r = t*B+b
__device__ float g_gie [Tz*Bz*H3];      // emb part of GRU input gates (+b_ih)
__device__ float g_Wihc[DEC*H3];        // W_ih[:, 512:]  transposed -> [k][j]
__device__ float g_Whh [DEC*H3];        // W_hh transposed -> [k][j]
__device__ float g_h   [Bz*DEC];        // current hidden
__device__ float g_ctx [Bz*DEC];        // attention context
__device__ float g_part[8*Bz*H3];       // split-K partials
__device__ float g_Hseq[Tz*Bz*DEC];     // h_new per step, row r = t*B+b

// bf16 split buffers (reused sequentially across GEMMs)
__device__ bf16 g_Ahi[3200*2048];
__device__ bf16 g_Alo[3200*2048];
__device__ bf16 g_Bhi[10000*512];
__device__ bf16 g_Blo[10000*512];

// ====================== warp-MMA helpers (plain sm_103-safe) ======================
__device__ __forceinline__ uint32_t smem_to_u32(const void* p) {
    uint32_t a;
    asm("{ .reg .u64 t; cvta.to.shared.u64 t, %1; cvt.u32.u64 %0, t; }" : "=r"(a) : "l"(p));
    return a;
}

#define LDSM_X4(R, ADDR) \
    asm volatile("ldmatrix.sync.aligned.m8n8.x4.shared.b16 {%0,%1,%2,%3}, [%4];" \
        : "=r"((R)[0]), "=r"((R)[1]), "=r"((R)[2]), "=r"((R)[3]) : "r"(ADDR))

#define MMA16816(D, A, B0, B1) \
    asm volatile("mma.sync.aligned.m16n8k16.row.col.f32.bf16.bf16.f32 " \
        "{%0,%1,%2,%3}, {%4,%5,%6,%7}, {%8,%9}, {%0,%1,%2,%3};" \
        : "+f"((D)[0]), "+f"((D)[1]), "+f"((D)[2]), "+f"((D)[3]) \
        : "r"((A)[0]), "r"((A)[1]), "r"((A)[2]), "r"((A)[3]), "r"(B0), "r"(B1))

// ====================== bf16 split preparation kernels ======================
__device__ __forceinline__ void split_one(float x, bf16* hi, bf16* lo, size_t i) {
    bf16 h = __float2bfloat16(x);
    hi[i] = h;
    lo[i] = __float2bfloat16(x - __bfloat162float(h));
}

__global__ void k_split(const float* __restrict__ src, bf16* hi, bf16* lo, int n)
{
    int i = blockIdx.x * blockDim.x + threadIdx.x;
    if (i < n) split_one(src[i], hi, lo, (size_t)i);
}

// src [rows][srcStride], take first cols -> dst [rows][cols]
__global__ void k_split_strided(const float* __restrict__ src, bf16* hi, bf16* lo,
                                int rows, int cols, int srcStride)
{
    int i = blockIdx.x * blockDim.x + threadIdx.x;
    if (i >= rows * cols) return;
    int r = i / cols, c = i - r * cols;
    split_one(src[(size_t)r * srcStride + c], hi, lo, (size_t)i);
}

// src [Ksrc][Nsrc] row-major -> dst [n][k]
__global__ void k_transpose_split(const float* __restrict__ src, bf16* hi, bf16* lo,
                                  int Ksrc, int Nsrc)
{
    int i = blockIdx.x * blockDim.x + threadIdx.x;
    if (i >= Ksrc * Nsrc) return;
    int k = i / Nsrc, n = i - k * Nsrc;
    split_one(src[i], hi, lo, (size_t)n * Ksrc + k);
}

// ====================== tensor-core split-bf16 GEMM (mma.sync) ======================
// C[M,N] = (Ahi+Alo)[M,K] @ (Bhi+Blo)[N,K]^T + bias   (3 MMA terms, fp32 accuracy)
// tile 128x128, BK=64, 256 threads = 8 warps (4 M x 2 N), warp tile 32x64.
// smem stride 72 bf16 (144B) -> conflict-free ldmatrix.
#define BKv      64
#define SSTRIDE  72
#define ATILE    (128 * SSTRIDE)                 // elems
#define MMA_SMEM (4 * ATILE * 2)                 // bytes = 73728

__global__ __launch_bounds__(256) void k_mma_gemm(
    const bf16* __restrict__ Ahi, const bf16* __restrict__ Alo,
    const bf16* __restrict__ Bhi, const bf16* __restrict__ Blo,
    const float* __restrict__ bias, float* __restrict__ C,
    int M, int N, int K, int remap)
{
    extern __shared__ bf16 sm[];
    bf16* sAh = sm;
    bf16* sAl = sm + ATILE;
    bf16* sBh = sm + 2 * ATILE;
    bf16* sBl = sm + 3 * ATILE;

    const int tid  = threadIdx.x;
    const int wid  = tid >> 5, lane = tid & 31;
    const int wm   = wid >> 1;        // 0..3 -> M offset wm*32
    const int wn   = wid & 1;         // 0..1 -> N offset wn*64
    const int mb   = blockIdx.y << 7, nb = blockIdx.x << 7;

    const uint32_t sbase = smem_to_u32(sm);
    const int lrow = lane & 15, lcol = (lane >> 4) * 8;

    // ldmatrix base byte-addresses (within-region), advance by ks*32B per k16 step
    uint32_t aAh[2], aAl[2], aBh[4], aBl[4];
    #pragma unroll
    for (int mi = 0; mi < 2; mi++) {
        uint32_t off = (uint32_t)((wm * 32 + mi * 16 + lrow) * SSTRIDE + lcol) * 2;
        aAh[mi] = sbase + off;
        aAl[mi] = sbase + (uint32_t)(ATILE * 2) + off;
    }
    #pragma unroll
    for (int nj = 0; nj < 4; nj++) {
        uint32_t off = (uint32_t)((wn * 64 + nj * 16 + lrow) * SSTRIDE + lcol) * 2;
        aBh[nj] = sbase + (uint32_t)(ATILE * 4) + off;
        aBl[nj] = sbase + (uint32_t)(ATILE * 6) + off;
    }

    float acc[2][8][4] = {};

    const int nchunks = K >> 6;
    for (int c = 0; c < nchunks; c++) {
        const int k0 = c << 6;
        const uint4 z = make_uint4(0u, 0u, 0u, 0u);
        #pragma unroll
        for (int u = 0; u < 4; u++) {
            int q = tid + (u << 8);               // 0..1023
            int r = q >> 3, g = q & 7;            // row 0..127, 16B group 0..7
            int so = r * SSTRIDE + g * 8;         // elem offset (16B aligned in bytes)
            uint4 vh = z, vl = z;
            if (mb + r < M) {
                size_t idx = (size_t)(mb + r) * K + k0 + g * 8;
                vh = *reinterpret_cast<const uint4*>(Ahi + idx);
                vl = *reinterpret_cast<const uint4*>(Alo + idx);
            }
            *reinterpret_cast<uint4*>(sAh + so) = vh;
            *reinterpret_cast<uint4*>(sAl + so) = vl;
            uint4 wh = z, wl = z;
            if (nb + r < N) {
                size_t idx = (size_t)(nb + r) * K + k0 + g * 8;
                wh = *reinterpret_cast<const uint4*>(Bhi + idx);
                wl = *reinterpret_cast<const uint4*>(Blo + idx);
            }
            *reinterpret_cast<uint4*>(sBh + so) = wh;
            *reinterpret_cast<uint4*>(sBl + so) = wl;
        }
        __syncthreads();

        #pragma unroll
        for (int ks = 0; ks < 4; ks++) {
            const uint32_t kb = ks * 32;          // bytes: 16 elems per k-step
            uint32_t ah[2][4], al[2][4], bh[4][4], bl[4][4];
            #pragma unroll
            for (int mi = 0; mi < 2; mi++) {
                LDSM_X4(ah[mi], aAh[mi] + kb);
                LDSM_X4(al[mi], aAl[mi] + kb);
            }
            #pragma unroll
            for (int nj = 0; nj < 4; nj++) {
                LDSM_X4(bh[nj], aBh[nj] + kb);
                LDSM_X4(bl[nj], aBl[nj] + kb);
            }
            #pragma unroll
            for (int mi = 0; mi < 2; mi++) {
                #pragma unroll
                for (int nj = 0; nj < 4; nj++) {
                    // x4 on B: matrices {0,2} = n-sub0 (b0,b1), {1,3} = n-sub1
                    MMA16816(acc[mi][nj * 2 + 0], ah[mi], bh[nj][0], bh[nj][2]);
                    MMA16816(acc[mi][nj * 2 + 1], ah[mi], bh[nj][1], bh[nj][3]);
                    MMA16816(acc[mi][nj * 2 + 0], ah[mi], bl[nj][0], bl[nj][2]);
                    MMA16816(acc[mi][nj * 2 + 1], ah[mi], bl[nj][1], bl[nj][3]);
                    MMA16816(acc[mi][nj * 2 + 0], al[mi], bh[nj][0], bh[nj][2]);
                    MMA16816(acc[mi][nj * 2 + 1], al[mi], bh[nj][1], bh[nj][3]);
                }
            }
        }
        __syncthreads();
    }

    // epilogue: d0,d1 -> row base + lane/4; d2,d3 -> +8. col = ... + (lane&3)*2
    #pragma unroll
    for (int mi = 0; mi < 2; mi++) {
        #pragma unroll
        for (int half = 0; half < 2; half++) {
            int row = mb + wm * 32 + mi * 16 + (lane >> 2) + half * 8;
            if (row >= M) continue;
            size_t rb;
            if (remap) { int tq = row >> 6, bb = row & 63; rb = (size_t)(bb * Tz + tq) * N; }
            else       { rb = (size_t)row * N; }
            #pragma unroll
            for (int nf = 0; nf < 8; nf++) {
                int col = nb + wn * 64 + nf * 8 + (lane & 3) * 2;
                if (col < N) {     // N even -> col+1 also valid
                    float2 v;
                    v.x = acc[mi][nf][half * 2 + 0] + bias[col];
                    v.y = acc[mi][nf][half * 2 + 1] + bias[col + 1];
                    *reinterpret_cast<float2*>(C + rb + col) = v;
                }
            }
        }
    }
}

// ====================== init / transpose / recurrent loop ======================
__global__ void k_init(const int* __restrict__ cap, const float* __restrict__ emb)
{
    int i = blockIdx.x * blockDim.x + threadIdx.x;   // T*B*EMB threads
    if (i < Bz * DEC) g_h[i] = 0.f;
    int d = i & 511;
    int r = i >> 9;            // t*B + b
    int t = r >> 6;
    int b = r & 63;
    int tok = cap[b * Tz + t];
    g_Xemb[i] = emb[(size_t)tok * EMBD + d];
}

__global__ void k_transpose(const float* __restrict__ W_ih, const float* __restrict__ W_hh)
{
    int i = blockIdx.x * blockDim.x + threadIdx.x;   // DEC*H3
    if (i >= DEC * H3) return;
    int j = i >> 9;       // 0..1535
    int k = i & 511;
    g_Wihc[k * H3 + j] = W_ih[j * (EMBD + DEC) + EMBD + k];
    g_Whh [k * H3 + j] = W_hh[j * DEC + k];
}

// per-step dual GEMM (gi_c and gh), split-K=4: grid (24, 4, 2), 256 threads
__global__ __launch_bounds__(256) void k_stepgemm()
{
    __shared__ float sA[16][68];
    __shared__ float sB[16][64];
    const int tid = threadIdx.x;
    const int tx = tid & 15, ty = tid >> 4;
    const int nb = blockIdx.x << 6;
    const int kbase = blockIdx.y << 7;
    const int z = blockIdx.z;
    const float* A  = z ? g_h   : g_ctx;
    const float* Bw = z ? g_Whh : g_Wihc;
    float* out = &g_part[(size_t)((z * 4 + blockIdx.y) * Bz) * H3];
    float acc[4][4] = {};
    const int arow = tid >> 2, akq = (tid & 3) << 2;
    const int brow = tid >> 4, bcol = (tid & 15) << 2;

    for (int kc = 0; kc < 128; kc += 16) {
        int k0 = kbase + kc;
        float4 av = *reinterpret_cast<const float4*>(&A[arow * DEC + k0 + akq]);
        sA[akq + 0][arow] = av.x; sA[akq + 1][arow] = av.y;
        sA[akq + 2][arow] = av.z; sA[akq + 3][arow] = av.w;
        float4 bv = *reinterpret_cast<const float4*>(&Bw[(size_t)(k0 + brow) * H3 + nb + bcol]);
        *reinterpret_cast<float4*>(&sB[brow][bcol]) = bv;
        __syncthreads();
        #pragma unroll
        for (int kk = 0; kk < 16; kk++) {
            float4 a = *reinterpret_cast<const float4*>(&sA[kk][ty * 4]);
            float4 b = *reinterpret_cast<const float4*>(&sB[kk][tx * 4]);
            float avr[4] = {a.x, a.y, a.z, a.w};
            float bvr[4] = {b.x, b.y, b.z, b.w};
            #pragma unroll
            for (int i = 0; i < 4; i++)
                #pragma unroll
                for (int j = 0; j < 4; j++)
                    acc[i][j] += avr[i] * bvr[j];
        }
        __syncthreads();
    }
    #pragma unroll
    for (int i = 0; i < 4; i++)
        #pragma unroll
        for (int j = 0; j < 4; j++)
            out[(size_t)(ty * 4 + i) * H3 + nb + tx * 4 + j] = acc[i][j];
}

__device__ __forceinline__ float gru_update(int r, int b, int d, const float* __restrict__ b_hh)
{
    const float* gie = &g_gie[(size_t)r * H3];
    float ir = gie[d], iz = gie[DEC + d], in_ = gie[2 * DEC + d];
    float hr = b_hh[d], hz = b_hh[DEC + d], hn = b_hh[2 * DEC + d];
    #pragma unroll
    for (int s = 0; s < 4; s++) {
        const float* p = &g_part[(size_t)(s * Bz + b) * H3];
        ir += p[d]; iz += p[DEC + d]; in_ += p[2 * DEC + d];
        const float* q = &g_part[(size_t)((4 + s) * Bz + b) * H3];
        hr += q[d]; hz += q[DEC + d]; hn += q[2 * DEC + d];
    }
    float rr = 1.f / (1.f + expf(-(ir + hr)));
    float zz = 1.f / (1.f + expf(-(iz + hz)));
    float nn = tanhf(in_ + rr * hn);
    float hp = g_h[b * DEC + d];
    return (1.f - zz) * nn + zz * hp;
}

// fused gates(t-1) -> h_t -> Bahdanau attention. grid 32 blocks x 2 batch rows.
__global__ __launch_bounds__(256) void k_att(
    int t,
    const float* __restrict__ W_da, const float* __restrict__ b_da,
    const float* __restrict__ W_fa, const float* __restrict__ b_hh)
{
    __shared__ float sh_h [2][DEC];
    __shared__ float sh_a2[2][ATTD];
    __shared__ float sh_sc[2][64];
    const int tid = threadIdx.x;
    const int b0 = blockIdx.x << 1;

    if (t > 0) {
        #pragma unroll
        for (int ii = 0; ii < 4; ii++) {
            int idx = tid + (ii << 8);          // 0..1023
            int bi = idx >> 9, d = idx & 511;
            int b = b0 + bi;
            int r = (t - 1) * Bz + b;
            float hv = gru_update(r, b, d, b_hh);
            sh_h[bi][d] = hv;
            g_h[b * DEC + d] = hv;
            g_Hseq[(size_t)r * DEC + d] = hv;
        }
    } else {
        #pragma unroll
        for (int ii = 0; ii < 4; ii++) {
            int idx = tid + (ii << 8);
            sh_h[idx >> 9][idx & 511] = 0.f;
        }
    }
    __syncthreads();

    // att2[bi][j] = h[bi] @ W_da[:,j] + b_da[j]
    {
        int j = tid;
        float a0 = b_da[j], a1 = a0;
        #pragma unroll 8
        for (int k = 0; k < DEC; k++) {
            float w = W_da[k * ATTD + j];
            a0 += sh_h[0][k] * w;
            a1 += sh_h[1][k] * w;
        }
        sh_a2[0][j] = a0; sh_a2[1][j] = a1;
    }
    __syncthreads();

    // scores: warp per (bi,l) pair
    {
        int warp = tid >> 5, lane = tid & 31;
        float wfa[8];
        #pragma unroll
        for (int q = 0; q < 8; q++) wfa[q] = W_fa[lane + 32 * q];
        for (int p = warp; p < 2 * Lz; p += 8) {
            int bi = (p >= Lz) ? 1 : 0;
            int l = p - bi * Lz;
            const float* arow = &g_att1[((size_t)(b0 + bi) * Lz + l) * ATTD];
            float s = 0.f;
            #pragma unroll
            for (int q = 0; q < 8; q++) {
                int j = lane + 32 * q;
                s += tanhf(arow[j] + sh_a2[bi][j]) * wfa[q];
            }
            #pragma unroll
            for (int o = 16; o; o >>= 1) s += __shfl_xor_sync(0xffffffffu, s, o);
            if (lane == 0) sh_sc[bi][l] = s;
        }
    }
    __syncthreads();

    // softmax over L=49
    if (tid < 2) {
        float mx = -1e30f;
        for (int l = 0; l < Lz; l++) mx = fmaxf(mx, sh_sc[tid][l]);
        float sum = 0.f;
        for (int l = 0; l < Lz; l++) { float e = expf(sh_sc[tid][l] - mx); sh_sc[tid][l] = e; sum += e; }
        float inv = 1.f / sum;
        for (int l = 0; l < Lz; l++) sh_sc[tid][l] *= inv;
    }
    __syncthreads();

    // context
    {
        int d = tid;
        #pragma unroll
        for (int bi = 0; bi < 2; bi++) {
            const float* erow = &g_enc[(size_t)(b0 + bi) * Lz * DEC];
            float c0 = 0.f, c1 = 0.f;
            for (int l = 0; l < Lz; l++) {
                float al = sh_sc[bi][l];
                c0 += al * erow[l * DEC + d];
                c1 += al * erow[l * DEC + 256 + d];
            }
            g_ctx[(b0 + bi) * DEC + d]       = c0;
            g_ctx[(b0 + bi) * DEC + 256 + d] = c1;
        }
    }
}

__global__ void k_gates(int t, const float* __restrict__ b_hh)
{
    int b = blockIdx.x, d = threadIdx.x;
    int r = t * Bz + b;
    float hv = gru_update(r, b, d, b_hh);
    g_h[b * DEC + d] = hv;
    g_Hseq[(size_t)r * DEC + d] = hv;
}

// ====================== launcher ======================
extern "C" void kernel_launch(void* const* d_in, const int* in_sizes, int n_in,
                              void* d_out, int out_size)
{
    (void)in_sizes; (void)n_in; (void)out_size;
    const float* spatial = (const float*)d_in[0];
    const int*   cap     = (const int*)  d_in[1];
    const float* W_feat  = (const float*)d_in[2];
    const float* b_feat  = (const float*)d_in[3];
    const float* W_ea    = (const float*)d_in[4];
    const float* b_ea    = (const float*)d_in[5];
    const float* W_da    = (const float*)d_in[6];
    const float* b_da    = (const float*)d_in[7];
    const float* W_fa    = (const float*)d_in[8];
    /* b_fa (d_in[9]) softmax-invariant */
    const float* emb     = (const float*)d_in[10];
    const float* W_ih    = (const float*)d_in[11];
    const float* W_hh    = (const float*)d_in[12];
    const float* b_ih    = (const float*)d_in[13];
    const float* b_hh    = (const float*)d_in[14];
    const float* W_fc    = (const float*)d_in[15];
    const float* b_fc    = (const float*)d_in[16];
    float* out = (float*)d_out;

    float *p_enc, *p_att1, *p_xemb, *p_gie, *p_hseq;
    bf16 *p_ahi, *p_alo, *p_bhi, *p_blo;
    cudaGetSymbolAddress((void**)&p_enc,  g_enc);
    cudaGetSymbolAddress((void**)&p_att1, g_att1);
    cudaGetSymbolAddress((void**)&p_xemb, g_Xemb);
    cudaGetSymbolAddress((void**)&p_gie,  g_gie);
    cudaGetSymbolAddress((void**)&p_hseq, g_Hseq);
    cudaGetSymbolAddress((void**)&p_ahi,  g_Ahi);
    cudaGetSymbolAddress((void**)&p_alo,  g_Alo);
    cudaGetSymbolAddress((void**)&p_bhi,  g_Bhi);
    cudaGetSymbolAddress((void**)&p_blo,  g_Blo);

    cudaFuncSetAttribute(k_mma_gemm, cudaFuncAttributeMaxDynamicSharedMemorySize, MMA_SMEM);

    const int SM = Bz * Lz;      // 3136
    const int SR = Tz * Bz;      // 3200

    // setup
    k_init<<<Tz * Bz, EMBD>>>(cap, emb);
    k_transpose<<<(DEC * H3 + 255) / 256, 256>>>(W_ih, W_hh);

    // ---- enc = spatial @ W_feat + b_feat  [3136, 512] ----
    k_split<<<(SM * ENCD + 255) / 256, 256>>>(spatial, p_ahi, p_alo, SM * ENCD);
    k_transpose_split<<<(ENCD * DEC + 255) / 256, 256>>>(W_feat, p_bhi, p_blo, ENCD, DEC);
    k_mma_gemm<<<dim3(DEC / 128, (SM + 127) / 128), 256, MMA_SMEM>>>(
        p_ahi, p_alo, p_bhi, p_blo, b_feat, p_enc, SM, DEC, ENCD, 0);

    // ---- att1 = enc @ W_ea + b_ea  [3136, 256] ----
    k_split<<<(SM * DEC + 255) / 256, 256>>>(p_enc, p_ahi, p_alo, SM * DEC);
    k_transpose_split<<<(DEC * ATTD + 255) / 256, 256>>>(W_ea, p_bhi, p_blo, DEC, ATTD);
    k_mma_gemm<<<dim3(ATTD / 128, (SM + 127) / 128), 256, MMA_SMEM>>>(
        p_ahi, p_alo, p_bhi, p_blo, b_ea, p_att1, SM, ATTD, DEC, 0);

    // ---- gie = Xemb @ W_ih[:, :512]^T + b_ih  [3200, 1536] ----
    k_split<<<(SR * EMBD + 255) / 256, 256>>>(p_xemb, p_ahi, p_alo, SR * EMBD);
    k_split_strided<<<(H3 * DEC + 255) / 256, 256>>>(W_ih, p_bhi, p_blo, H3, DEC, EMBD + DEC);
    k_mma_gemm<<<dim3(H3 / 128, SR / 128), 256, MMA_SMEM>>>(
        p_ahi, p_alo, p_bhi, p_blo, b_ih, p_gie, SR, H3, DEC, 0);

    // ---- sequential decode ----
    for (int t = 0; t < Tz; t++) {
        k_att<<<32, 256>>>(t, W_da, b_da, W_fa, b_hh);
        k_stepgemm<<<dim3(24, 4, 2), 256>>>();
    }
    k_gates<<<Bz, DEC>>>(Tz - 1, b_hh);

    // ---- fc: logits = Hseq @ W_fc + b_fc, remapped to [B, T, V] ----
    k_split<<<(SR * DEC + 255) / 256, 256>>>(p_hseq, p_ahi, p_alo, SR * DEC);
    k_transpose_split<<<(DEC * VOC + 255) / 256, 256>>>(W_fc, p_bhi, p_blo, DEC, VOC);
    k_mma_gemm<<<dim3((VOC + 127) / 128, SR / 128), 256, MMA_SMEM>>>(
        p_ahi, p_alo, p_bhi, p_blo, b_fc, out, SR, VOC, DEC, 1);
}

// round 10
// speedup vs baseline: 1.9480x; 1.0881x over previous
#include <cuda_runtime.h>
#include <cuda_bf16.h>
#include <math.h>
#include <stdint.h>

#define Bz   64
#define Lz   49
#define ENCD 2048
#define DEC  512
#define ATTD 256
#define VOC  10000
#define Tz   50
#define H3   1536
#define EMBD 512

typedef __nv_bfloat16 bf16;

// ---------------- scratch (device globals; no runtime alloc) ----------------
__device__ float g_enc [Bz*Lz*DEC];     // [B,L,DEC]
__device__ float g_att1[Bz*Lz*ATTD];    // [B,L,ATT]
__device__ float g_gie [Tz*Bz*H3];      // emb part of GRU input gates (+b_ih)
__device__ float g_h   [Bz*DEC];        // current hidden (fp32, for z*h term)
__device__ float g_part[2*Bz*H3];       // per-step gate partials: [mat][b][j]

// bf16 split operand buffers.
// g_Ahi/g_Alo regions: [0, 3136*2048) spatial / enc-split (reused),
//   XE_OFF = 3200*2048 : Xemb split (3200x512),
//   HS_OFF = XE_OFF + 3200*512 : Hseq split (3200x512) for fc.
#define XE_OFF (3200*2048)
#define HS_OFF (XE_OFF + 3200*512)
__device__ bf16 g_Ahi[3200*2048 + 2*3200*512];
__device__ bf16 g_Alo[3200*2048 + 2*3200*512];
__device__ bf16 g_Bhi[10000*512];
__device__ bf16 g_Blo[10000*512];
__device__ bf16 g_Whi[2*H3*DEC];        // mat0 = W_ih[:,512:], mat1 = W_hh (row j, col k)
__device__ bf16 g_Wlo[2*H3*DEC];
__device__ bf16 g_hhi[Bz*DEC], g_hlo[Bz*DEC];   // current h split
__device__ bf16 g_chi[Bz*DEC], g_clo[Bz*DEC];   // current ctx split

// ====================== PTX helpers (plain sm_103-safe) ======================
__device__ __forceinline__ uint32_t smem_to_u32(const void* p) {
    uint32_t a;
    asm("{ .reg .u64 t; cvta.to.shared.u64 t, %1; cvt.u32.u64 %0, t; }" : "=r"(a) : "l"(p));
    return a;
}

#define LDSM_X4(R, ADDR) \
    asm volatile("ldmatrix.sync.aligned.m8n8.x4.shared.b16 {%0,%1,%2,%3}, [%4];" \
        : "=r"((R)[0]), "=r"((R)[1]), "=r"((R)[2]), "=r"((R)[3]) : "r"(ADDR))

#define MMA16816(D, A, B0, B1) \
    asm volatile("mma.sync.aligned.m16n8k16.row.col.f32.bf16.bf16.f32 " \
        "{%0,%1,%2,%3}, {%4,%5,%6,%7}, {%8,%9}, {%0,%1,%2,%3};" \
        : "+f"((D)[0]), "+f"((D)[1]), "+f"((D)[2]), "+f"((D)[3]) \
        : "r"((A)[0]), "r"((A)[1]), "r"((A)[2]), "r"((A)[3]), "r"(B0), "r"(B1))

#define CP16(dst, src, sz) \
    asm volatile("cp.async.cg.shared.global [%0], [%1], 16, %2;" \
        :: "r"(dst), "l"(src), "r"(sz) : "memory")
#define CP_COMMIT() asm volatile("cp.async.commit_group;" ::: "memory")
#define CP_WAIT1()  asm volatile("cp.async.wait_group 1;" ::: "memory")
#define CP_WAIT0()  asm volatile("cp.async.wait_group 0;" ::: "memory")

__device__ __forceinline__ void split_store(float x, bf16* hi, bf16* lo, size_t i) {
    bf16 h = __float2bfloat16(x);
    hi[i] = h;
    lo[i] = __float2bfloat16(x - __bfloat162float(h));
}

// ====================== prep kernels ======================
// gather embeddings + split directly; zero h
__global__ void k_init(const int* __restrict__ cap, const float* __restrict__ emb)
{
    int i = blockIdx.x * blockDim.x + threadIdx.x;   // 3200*512 threads
    if (i < Bz * DEC) g_h[i] = 0.f;
    int d = i & 511;
    int r = i >> 9;            // t*B + b
    int t = r >> 6;
    int b = r & 63;
    int tok = cap[b * Tz + t];
    split_store(emb[(size_t)tok * EMBD + d], g_Ahi + XE_OFF, g_Alo + XE_OFF, (size_t)i);
}

// W_ih[:,512:] and W_hh -> bf16 hi/lo, [j][k] (already K-major, no transpose)
__global__ void k_prepW(const float* __restrict__ W_ih, const float* __restrict__ W_hh)
{
    int i = blockIdx.x * blockDim.x + threadIdx.x;
    if (i >= 2 * H3 * DEC) return;
    int mat = i / (H3 * DEC);
    int rem = i - mat * (H3 * DEC);
    int j = rem >> 9, k = rem & 511;
    float x = (mat == 0) ? W_ih[j * (EMBD + DEC) + EMBD + k] : W_hh[j * DEC + k];
    split_store(x, g_Whi, g_Wlo, (size_t)i);
}

__global__ void k_split(const float* __restrict__ src, bf16* hi, bf16* lo, int n)
{
    int i = blockIdx.x * blockDim.x + threadIdx.x;
    if (i < n) split_store(src[i], hi, lo, (size_t)i);
}

// src [rows][srcStride], take first cols -> dst [rows][cols]  (for gie B = W_ih[:, :512])
__global__ void k_split_strided(const float* __restrict__ src, bf16* hi, bf16* lo,
                                int rows, int cols, int srcStride)
{
    int i = blockIdx.x * blockDim.x + threadIdx.x;
    if (i >= rows * cols) return;
    int r = i / cols, c = i - r * cols;
    split_store(src[(size_t)r * srcStride + c], hi, lo, (size_t)i);
}

// src [Ksrc][Nsrc] row-major -> dst [n][k]
__global__ void k_transpose_split(const float* __restrict__ src, bf16* hi, bf16* lo,
                                  int Ksrc, int Nsrc)
{
    int i = blockIdx.x * blockDim.x + threadIdx.x;
    if (i >= Ksrc * Nsrc) return;
    int k = i / Nsrc, n = i - k * Nsrc;
    split_store(src[i], hi, lo, (size_t)n * Ksrc + k);
}

// ====================== pipelined split-bf16 GEMM (mma.sync + cp.async) ======================
// C[M,N] = (Ahi+Alo)[M,K] @ (Bhi+Blo)[N,K]^T + bias, 3 MMA terms.
// tile 128x128, BK=64, 2-stage cp.async double buffer. 8 warps (4M x 2N).
#define SSTRIDE  72
#define ATILE    (128 * SSTRIDE)      // elems per region
#define ATILE2   (ATILE * 2)          // bytes per region = 18432
#define STAGEB   (4 * ATILE2)         // bytes per stage  = 73728
#define MMA_SMEM (2 * STAGEB)         // 147456

__global__ __launch_bounds__(256) void k_mma_gemm(
    const bf16* __restrict__ Ahi, const bf16* __restrict__ Alo,
    const bf16* __restrict__ Bhi, const bf16* __restrict__ Blo,
    const float* __restrict__ bias, float* __restrict__ C,
    int M, int N, int K, int remap)
{
    extern __shared__ bf16 sm[];
    const int tid  = threadIdx.x;
    const int wid  = tid >> 5, lane = tid & 31;
    const int wm   = wid >> 1, wn = wid & 1;
    const int mb   = blockIdx.y << 7, nb = blockIdx.x << 7;
    const uint32_t sbase = smem_to_u32(sm);
    const int lrow = lane & 15, lcol = (lane >> 4) * 8;

    // ldmatrix offsets relative to stage base (bytes)
    uint32_t oA[2], oB[4];
    #pragma unroll
    for (int mi = 0; mi < 2; mi++)
        oA[mi] = (uint32_t)(((wm * 32 + mi * 16 + lrow) * SSTRIDE + lcol) * 2);
    #pragma unroll
    for (int nj = 0; nj < 4; nj++)
        oB[nj] = (uint32_t)(2 * ATILE2 + ((wn * 64 + nj * 16 + lrow) * SSTRIDE + lcol) * 2);

    const int rload = tid >> 3, gload = tid & 7;

    float acc[2][8][4] = {};
    const int nchunks = K >> 6;

    auto issue = [&](int c, int s) {
        const int k0 = c << 6;
        const uint32_t sb = sbase + (uint32_t)s * STAGEB;
        #pragma unroll
        for (int u = 0; u < 4; u++) {
            int r = rload + u * 32;
            uint32_t so = (uint32_t)((r * SSTRIDE + gload * 8) * 2);
            int ra = mb + r;
            unsigned za = (ra < M) ? 16u : 0u;
            if (ra >= M) ra = 0;
            const bf16* pa = Ahi + (size_t)ra * K + k0 + gload * 8;
            const bf16* pl = Alo + (size_t)ra * K + k0 + gload * 8;
            CP16(sb + so, pa, za);
            CP16(sb + ATILE2 + so, pl, za);
            int rb = nb + r;
            unsigned zb = (rb < N) ? 16u : 0u;
            if (rb >= N) rb = 0;
            const bf16* pb = Bhi + (size_t)rb * K + k0 + gload * 8;
            const bf16* pq = Blo + (size_t)rb * K + k0 + gload * 8;
            CP16(sb + 2 * ATILE2 + so, pb, zb);
            CP16(sb + 3 * ATILE2 + so, pq, zb);
        }
    };

    issue(0, 0); CP_COMMIT();

    for (int c = 0; c < nchunks; c++) {
        if (c + 1 < nchunks) { issue(c + 1, (c + 1) & 1); CP_COMMIT(); CP_WAIT1(); }
        else                 { CP_WAIT0(); }
        __syncthreads();

        const uint32_t sb = sbase + (uint32_t)(c & 1) * STAGEB;
        #pragma unroll
        for (int ks = 0; ks < 4; ks++) {
            const uint32_t kb = ks * 32;
            uint32_t ah[2][4], al[2][4], bh[4][4], bl[4][4];
            #pragma unroll
            for (int mi = 0; mi < 2; mi++) {
                LDSM_X4(ah[mi], sb + oA[mi] + kb);
                LDSM_X4(al[mi], sb + ATILE2 + oA[mi] + kb);
            }
            #pragma unroll
            for (int nj = 0; nj < 4; nj++) {
                LDSM_X4(bh[nj], sb + oB[nj] + kb);
                LDSM_X4(bl[nj], sb + ATILE2 + oB[nj] + kb);
            }
            #pragma unroll
            for (int mi = 0; mi < 2; mi++) {
                #pragma unroll
                for (int nj = 0; nj < 4; nj++) {
                    MMA16816(acc[mi][nj * 2 + 0], ah[mi], bh[nj][0], bh[nj][2]);
                    MMA16816(acc[mi][nj * 2 + 1], ah[mi], bh[nj][1], bh[nj][3]);
                    MMA16816(acc[mi][nj * 2 + 0], ah[mi], bl[nj][0], bl[nj][2]);
                    MMA16816(acc[mi][nj * 2 + 1], ah[mi], bl[nj][1], bl[nj][3]);
                    MMA16816(acc[mi][nj * 2 + 0], al[mi], bh[nj][0], bh[nj][2]);
                    MMA16816(acc[mi][nj * 2 + 1], al[mi], bh[nj][1], bh[nj][3]);
                }
            }
        }
        __syncthreads();
    }

    // epilogue
    #pragma unroll
    for (int mi = 0; mi < 2; mi++) {
        #pragma unroll
        for (int half = 0; half < 2; half++) {
            int row = mb + wm * 32 + mi * 16 + (lane >> 2) + half * 8;
            if (row >= M) continue;
            size_t rb;
            if (remap) { int tq = row >> 6, bb = row & 63; rb = (size_t)(bb * Tz + tq) * N; }
            else       { rb = (size_t)row * N; }
            #pragma unroll
            for (int nf = 0; nf < 8; nf++) {
                int col = nb + wn * 64 + nf * 8 + (lane & 3) * 2;
                if (col < N) {
                    float2 v;
                    v.x = acc[mi][nf][half * 2 + 0] + bias[col];
                    v.y = acc[mi][nf][half * 2 + 1] + bias[col + 1];
                    *reinterpret_cast<float2*>(C + rb + col) = v;
                }
            }
        }
    }
}

// ====================== per-step GEMM on tensor cores ======================
// grid (12, 2): mat 0: gi_c = ctx @ Wihc^T ; mat 1: gh = h @ Whh^T. 64x128 tile, K=512.
#define SGA2    (64 * SSTRIDE * 2)            // 9216 bytes
#define SGB2    (128 * SSTRIDE * 2)           // 18432 bytes
#define SG_SMEM (2 * SGA2 + 2 * SGB2)         // 55296

__global__ __launch_bounds__(256) void k_stepgemm_mma()
{
    extern __shared__ bf16 sm[];
    const int tid = threadIdx.x, wid = tid >> 5, lane = tid & 31;
    const int wm = wid >> 2, wn = wid & 3;
    const int nb = blockIdx.x << 7;
    const int mat = blockIdx.y;
    const bf16* Ahi_ = mat ? g_hhi : g_chi;
    const bf16* Alo_ = mat ? g_hlo : g_clo;
    const bf16* Bh_  = g_Whi + (size_t)mat * H3 * DEC;
    const bf16* Bl_  = g_Wlo + (size_t)mat * H3 * DEC;
    float* out = g_part + (size_t)mat * Bz * H3;

    const uint32_t sbase = smem_to_u32(sm);
    const uint32_t oBh0 = 2 * SGA2, oBl0 = 2 * SGA2 + SGB2;
    const int lrow = lane & 15, lcol = (lane >> 4) * 8;
    uint32_t oA[2], oB[2];
    #pragma unroll
    for (int mi = 0; mi < 2; mi++)
        oA[mi] = (uint32_t)(((wm * 32 + mi * 16 + lrow) * SSTRIDE + lcol) * 2);
    #pragma unroll
    for (int nj = 0; nj < 2; nj++)
        oB[nj] = (uint32_t)(((wn * 32 + nj * 16 + lrow) * SSTRIDE + lcol) * 2);

    float acc[2][4][4] = {};
    const int rl = tid >> 3, gl = tid & 7;
    char* smc = (char*)sm;

    for (int c = 0; c < 8; c++) {
        int k0 = c << 6;
        #pragma unroll
        for (int u = 0; u < 2; u++) {
            int r = rl + u * 32;
            uint32_t so = (uint32_t)((r * SSTRIDE + gl * 8) * 2);
            size_t gi = (size_t)r * DEC + k0 + gl * 8;
            *reinterpret_cast<uint4*>(smc + so)        = *reinterpret_cast<const uint4*>(Ahi_ + gi);
            *reinterpret_cast<uint4*>(smc + SGA2 + so) = *reinterpret_cast<const uint4*>(Alo_ + gi);
        }
        #pragma unroll
        for (int u = 0; u < 4; u++) {
            int r = rl + u * 32;
            uint32_t so = (uint32_t)((r * SSTRIDE + gl * 8) * 2);
            size_t gi = (size_t)(nb + r) * DEC + k0 + gl * 8;
            *reinterpret_cast<uint4*>(smc + oBh0 + so) = *reinterpret_cast<const uint4*>(Bh_ + gi);
            *reinterpret_cast<uint4*>(smc + oBl0 + so) = *reinterpret_cast<const uint4*>(Bl_ + gi);
        }
        __syncthreads();
        #pragma unroll
        for (int ks = 0; ks < 4; ks++) {
            uint32_t kb = ks * 32;
            uint32_t ah[2][4], al[2][4], bh[2][4], bl[2][4];
            #pragma unroll
            for (int mi = 0; mi < 2; mi++) {
                LDSM_X4(ah[mi], sbase + oA[mi] + kb);
                LDSM_X4(al[mi], sbase + SGA2 + oA[mi] + kb);
            }
            #pragma unroll
            for (int nj = 0; nj < 2; nj++) {
                LDSM_X4(bh[nj], sbase + oBh0 + oB[nj] + kb);
                LDSM_X4(bl[nj], sbase + oBl0 + oB[nj] + kb);
            }
            #pragma unroll
            for (int mi = 0; mi < 2; mi++) {
                #pragma unroll
                for (int nj = 0; nj < 2; nj++) {
                    MMA16816(acc[mi][nj * 2 + 0], ah[mi], bh[nj][0], bh[nj][2]);
                    MMA16816(acc[mi][nj * 2 + 1], ah[mi], bh[nj][1], bh[nj][3]);
                    MMA16816(acc[mi][nj * 2 + 0], ah[mi], bl[nj][0], bl[nj][2]);
                    MMA16816(acc[mi][nj * 2 + 1], ah[mi], bl[nj][1], bl[nj][3]);
                    MMA16816(acc[mi][nj * 2 + 0], al[mi], bh[nj][0], bh[nj][2]);
                    MMA16816(acc[mi][nj * 2 + 1], al[mi], bh[nj][1], bh[nj][3]);
                }
            }
        }
        __syncthreads();
    }

    #pragma unroll
    for (int mi = 0; mi < 2; mi++) {
        #pragma unroll
        for (int half = 0; half < 2; half++) {
            int row = wm * 32 + mi * 16 + (lane >> 2) + half * 8;
            #pragma unroll
            for (int nf = 0; nf < 4; nf++) {
                int col = nb + wn * 32 + nf * 8 + (lane & 3) * 2;
                float2 v;
                v.x = acc[mi][nf][half * 2 + 0];
                v.y = acc[mi][nf][half * 2 + 1];
                *reinterpret_cast<float2*>(out + (size_t)row * H3 + col) = v;
            }
        }
    }
}

// ====================== GRU combine + attention ======================
__device__ __forceinline__ float gru_update(int r, int b, int d, const float* __restrict__ b_hh)
{
    const float* gie = &g_gie[(size_t)r * H3];
    const float* p0 = &g_part[(size_t)b * H3];            // gi_c
    const float* p1 = &g_part[(size_t)(Bz + b) * H3];     // gh
    float ir  = gie[d]           + p0[d];
    float iz  = gie[DEC + d]     + p0[DEC + d];
    float in_ = gie[2 * DEC + d] + p0[2 * DEC + d];
    float hr  = b_hh[d]           + p1[d];
    float hz  = b_hh[DEC + d]     + p1[DEC + d];
    float hn  = b_hh[2 * DEC + d] + p1[2 * DEC + d];
    float rr = 1.f / (1.f + expf(-(ir + hr)));
    float zz = 1.f / (1.f + expf(-(iz + hz)));
    float nn = tanhf(in_ + rr * hn);
    float hp = g_h[b * DEC + d];
    return (1.f - zz) * nn + zz * hp;
}

// fused gates(t-1) -> h_t -> Bahdanau attention. grid 32 blocks x 2 batch rows.
__global__ __launch_bounds__(256) void k_att(
    int t,
    const float* __restrict__ W_da, const float* __restrict__ b_da,
    const float* __restrict__ W_fa, const float* __restrict__ b_hh)
{
    __shared__ float sh_h [2][DEC];
    __shared__ float sh_a2[2][ATTD];
    __shared__ float sh_sc[2][64];
    const int tid = threadIdx.x;
    const int b0 = blockIdx.x << 1;

    if (t > 0) {
        #pragma unroll
        for (int ii = 0; ii < 4; ii++) {
            int idx = tid + (ii << 8);          // 0..1023
            int bi = idx >> 9, d = idx & 511;
            int b = b0 + bi;
            int r = (t - 1) * Bz + b;
            float hv = gru_update(r, b, d, b_hh);
            sh_h[bi][d] = hv;
            g_h[b * DEC + d] = hv;
            bf16 hh = __float2bfloat16(hv);
            bf16 hl = __float2bfloat16(hv - __bfloat162float(hh));
            g_hhi[b * DEC + d] = hh;
            g_hlo[b * DEC + d] = hl;
            g_Ahi[HS_OFF + (size_t)r * DEC + d] = hh;
            g_Alo[HS_OFF + (size_t)r * DEC + d] = hl;
        }
    } else {
        bf16 zb = __float2bfloat16(0.f);
        #pragma unroll
        for (int ii = 0; ii < 4; ii++) {
            int idx = tid + (ii << 8);
            int bi = idx >> 9, d = idx & 511;
            sh_h[bi][d] = 0.f;
            g_hhi[(b0 + bi) * DEC + d] = zb;
            g_hlo[(b0 + bi) * DEC + d] = zb;
        }
    }
    __syncthreads();

    // att2[bi][j] = h[bi] @ W_da[:,j] + b_da[j]
    {
        int j = tid;
        float a0 = b_da[j], a1 = a0;
        #pragma unroll 8
        for (int k = 0; k < DEC; k++) {
            float w = W_da[k * ATTD + j];
            a0 += sh_h[0][k] * w;
            a1 += sh_h[1][k] * w;
        }
        sh_a2[0][j] = a0; sh_a2[1][j] = a1;
    }
    __syncthreads();

    // scores
    {
        int warp = tid >> 5, lane = tid & 31;
        float wfa[8];
        #pragma unroll
        for (int q = 0; q < 8; q++) wfa[q] = W_fa[lane + 32 * q];
        for (int p = warp; p < 2 * Lz; p += 8) {
            int bi = (p >= Lz) ? 1 : 0;
            int l = p - bi * Lz;
            const float* arow = &g_att1[((size_t)(b0 + bi) * Lz + l) * ATTD];
            float s = 0.f;
            #pragma unroll
            for (int q = 0; q < 8; q++) {
                int j = lane + 32 * q;
                s += tanhf(arow[j] + sh_a2[bi][j]) * wfa[q];
            }
            #pragma unroll
            for (int o = 16; o; o >>= 1) s += __shfl_xor_sync(0xffffffffu, s, o);
            if (lane == 0) sh_sc[bi][l] = s;
        }
    }
    __syncthreads();

    // softmax over L=49
    if (tid < 2) {
        float mx = -1e30f;
        for (int l = 0; l < Lz; l++) mx = fmaxf(mx, sh_sc[tid][l]);
        float sum = 0.f;
        for (int l = 0; l < Lz; l++) { float e = expf(sh_sc[tid][l] - mx); sh_sc[tid][l] = e; sum += e; }
        float inv = 1.f / sum;
        for (int l = 0; l < Lz; l++) sh_sc[tid][l] *= inv;
    }
    __syncthreads();

    // context -> bf16 hi/lo split
    {
        int d = tid;
        #pragma unroll
        for (int bi = 0; bi < 2; bi++) {
            const float* erow = &g_enc[(size_t)(b0 + bi) * Lz * DEC];
            float c0 = 0.f, c1 = 0.f;
            for (int l = 0; l < Lz; l++) {
                float al = sh_sc[bi][l];
                c0 += al * erow[l * DEC + d];
                c1 += al * erow[l * DEC + 256 + d];
            }
            int b = b0 + bi;
            split_store(c0, g_chi, g_clo, (size_t)b * DEC + d);
            split_store(c1, g_chi, g_clo, (size_t)b * DEC + 256 + d);
        }
    }
}

// final step's gate combine (t = T-1): only Hseq split needed
__global__ void k_gates(int t, const float* __restrict__ b_hh)
{
    int b = blockIdx.x, d = threadIdx.x;
    int r = t * Bz + b;
    float hv = gru_update(r, b, d, b_hh);
    split_store(hv, g_Ahi + HS_OFF, g_Alo + HS_OFF, (size_t)r * DEC + d);
}

// ====================== launcher ======================
extern "C" void kernel_launch(void* const* d_in, const int* in_sizes, int n_in,
                              void* d_out, int out_size)
{
    (void)in_sizes; (void)n_in; (void)out_size;
    const float* spatial = (const float*)d_in[0];
    const int*   cap     = (const int*)  d_in[1];
    const float* W_feat  = (const float*)d_in[2];
    const float* b_feat  = (const float*)d_in[3];
    const float* W_ea    = (const float*)d_in[4];
    const float* b_ea    = (const float*)d_in[5];
    const float* W_da    = (const float*)d_in[6];
    const float* b_da    = (const float*)d_in[7];
    const float* W_fa    = (const float*)d_in[8];
    /* b_fa (d_in[9]) softmax-invariant */
    const float* emb     = (const float*)d_in[10];
    const float* W_ih    = (const float*)d_in[11];
    const float* W_hh    = (const float*)d_in[12];
    const float* b_ih    = (const float*)d_in[13];
    const float* b_hh    = (const float*)d_in[14];
    const float* W_fc    = (const float*)d_in[15];
    const float* b_fc    = (const float*)d_in[16];
    float* out = (float*)d_out;

    float *p_enc, *p_att1, *p_gie;
    bf16 *p_ahi, *p_alo, *p_bhi, *p_blo;
    cudaGetSymbolAddress((void**)&p_enc,  g_enc);
    cudaGetSymbolAddress((void**)&p_att1, g_att1);
    cudaGetSymbolAddress((void**)&p_gie,  g_gie);
    cudaGetSymbolAddress((void**)&p_ahi,  g_Ahi);
    cudaGetSymbolAddress((void**)&p_alo,  g_Alo);
    cudaGetSymbolAddress((void**)&p_bhi,  g_Bhi);
    cudaGetSymbolAddress((void**)&p_blo,  g_Blo);

    cudaFuncSetAttribute(k_mma_gemm, cudaFuncAttributeMaxDynamicSharedMemorySize, MMA_SMEM);
    cudaFuncSetAttribute(k_stepgemm_mma, cudaFuncAttributeMaxDynamicSharedMemorySize, SG_SMEM);

    const int SM = Bz * Lz;      // 3136
    const int SR = Tz * Bz;      // 3200

    // setup: gather+split embeddings, zero h, split recurrent weights
    k_init<<<SR, EMBD>>>(cap, emb);
    k_prepW<<<(2 * H3 * DEC + 255) / 256, 256>>>(W_ih, W_hh);

    // ---- enc = spatial @ W_feat + b_feat  [3136, 512] ----
    k_split<<<(SM * ENCD + 255) / 256, 256>>>(spatial, p_ahi, p_alo, SM * ENCD);
    k_transpose_split<<<(ENCD * DEC + 255) / 256, 256>>>(W_feat, p_bhi, p_blo, ENCD, DEC);
    k_mma_gemm<<<dim3(DEC / 128, (SM + 127) / 128), 256, MMA_SMEM>>>(
        p_ahi, p_alo, p_bhi, p_blo, b_feat, p_enc, SM, DEC, ENCD, 0);

    // ---- att1 = enc @ W_ea + b_ea  [3136, 256] ----
    k_split<<<(SM * DEC + 255) / 256, 256>>>(p_enc, p_ahi, p_alo, SM * DEC);
    k_transpose_split<<<(DEC * ATTD + 255) / 256, 256>>>(W_ea, p_bhi, p_blo, DEC, ATTD);
    k_mma_gemm<<<dim3(ATTD / 128, (SM + 127) / 128), 256, MMA_SMEM>>>(
        p_ahi, p_alo, p_bhi, p_blo, b_ea, p_att1, SM, ATTD, DEC, 0);

    // ---- gie = Xemb @ W_ih[:, :512]^T + b_ih  [3200, 1536] ----
    k_split_strided<<<(H3 * DEC + 255) / 256, 256>>>(W_ih, p_bhi, p_blo, H3, DEC, EMBD + DEC);
    k_mma_gemm<<<dim3(H3 / 128, SR / 128), 256, MMA_SMEM>>>(
        p_ahi + XE_OFF, p_alo + XE_OFF, p_bhi, p_blo, b_ih, p_gie, SR, H3, DEC, 0);

    // ---- sequential decode ----
    for (int t = 0; t < Tz; t++) {
        k_att<<<32, 256>>>(t, W_da, b_da, W_fa, b_hh);
        k_stepgemm_mma<<<dim3(12, 2), 256, SG_SMEM>>>();
    }
    k_gates<<<Bz, DEC>>>(Tz - 1, b_hh);

    // ---- fc: logits = Hseq @ W_fc + b_fc, remapped to [B, T, V] ----
    k_transpose_split<<<(DEC * VOC + 255) / 256, 256>>>(W_fc, p_bhi, p_blo, DEC, VOC);
    k_mma_gemm<<<dim3((VOC + 127) / 128, SR / 128), 256, MMA_SMEM>>>(
        p_ahi + HS_OFF, p_alo + HS_OFF, p_bhi, p_blo, b_fc, out, SR, VOC, DEC, 1);
}

// round 11
// speedup vs baseline: 2.1298x; 1.0933x over previous
#include <cuda_runtime.h>
#include <cuda_bf16.h>
#include <cuda_fp16.h>
#include <math.h>
#include <stdint.h>

#define Bz   64
#define Lz   49
#define ENCD 2048
#define DEC  512
#define ATTD 256
#define VOC  10000
#define Tz   50
#define H3   1536
#define EMBD 512

typedef __nv_bfloat16 bf16;

// ---------------- scratch (device globals; no runtime alloc) ----------------
__device__ float g_enc [Bz*Lz*DEC];     // [B,L,DEC]
__device__ float g_att1[Bz*Lz*ATTD];    // [B,L,ATT]
__device__ float g_gie [Tz*Bz*H3];      // emb part of GRU input gates (+b_ih)
__device__ float g_h   [Bz*DEC];        // current hidden (fp32)
__device__ float g_part[4*Bz*H3];       // [mat(2)*2+ksplit][b][j]
__device__ float g_WdaT[ATTD*DEC];      // W_da transposed -> [j][k]

// bf16 split operand buffers (3-term path).
#define XE_OFF (3200*2048)
__device__ bf16 g_Ahi[3200*2048 + 3200*512];
__device__ bf16 g_Alo[3200*2048 + 3200*512];
__device__ bf16 g_Bhi[10000*512];
__device__ bf16 g_Blo[10000*512];
__device__ bf16 g_Whi[2*H3*DEC];        // mat0 = W_ih[:,512:], mat1 = W_hh ([j][k])
__device__ bf16 g_Wlo[2*H3*DEC];
__device__ bf16 g_hhi[Bz*DEC], g_hlo[Bz*DEC];   // current h split
__device__ bf16 g_chi[Bz*DEC], g_clo[Bz*DEC];   // current ctx split

// fp16 single-term buffers (fc path)
__device__ half g_Hs16 [Tz*Bz*DEC];     // Hseq fp16, row r = t*B+b
__device__ half g_Wfc16[10000*512];     // W_fc^T fp16, [n][k]

// ====================== PTX helpers (plain sm_103-safe) ======================
__device__ __forceinline__ uint32_t smem_to_u32(const void* p) {
    uint32_t a;
    asm("{ .reg .u64 t; cvta.to.shared.u64 t, %1; cvt.u32.u64 %0, t; }" : "=r"(a) : "l"(p));
    return a;
}

#define LDSM_X4(R, ADDR) \
    asm volatile("ldmatrix.sync.aligned.m8n8.x4.shared.b16 {%0,%1,%2,%3}, [%4];" \
        : "=r"((R)[0]), "=r"((R)[1]), "=r"((R)[2]), "=r"((R)[3]) : "r"(ADDR))

#define MMA16816(D, A, B0, B1) \
    asm volatile("mma.sync.aligned.m16n8k16.row.col.f32.bf16.bf16.f32 " \
        "{%0,%1,%2,%3}, {%4,%5,%6,%7}, {%8,%9}, {%0,%1,%2,%3};" \
        : "+f"((D)[0]), "+f"((D)[1]), "+f"((D)[2]), "+f"((D)[3]) \
        : "r"((A)[0]), "r"((A)[1]), "r"((A)[2]), "r"((A)[3]), "r"(B0), "r"(B1))

#define MMA16816H(D, A, B0, B1) \
    asm volatile("mma.sync.aligned.m16n8k16.row.col.f32.f16.f16.f32 " \
        "{%0,%1,%2,%3}, {%4,%5,%6,%7}, {%8,%9}, {%0,%1,%2,%3};" \
        : "+f"((D)[0]), "+f"((D)[1]), "+f"((D)[2]), "+f"((D)[3]) \
        : "r"((A)[0]), "r"((A)[1]), "r"((A)[2]), "r"((A)[3]), "r"(B0), "r"(B1))

#define CP16(dst, src, sz) \
    asm volatile("cp.async.cg.shared.global [%0], [%1], 16, %2;" \
        :: "r"(dst), "l"(src), "r"(sz) : "memory")
#define CP_COMMIT() asm volatile("cp.async.commit_group;" ::: "memory")
#define CP_WAIT1()  asm volatile("cp.async.wait_group 1;" ::: "memory")
#define CP_WAIT0()  asm volatile("cp.async.wait_group 0;" ::: "memory")

__device__ __forceinline__ void split_store(float x, bf16* hi, bf16* lo, size_t i) {
    bf16 h = __float2bfloat16(x);
    hi[i] = h;
    lo[i] = __float2bfloat16(x - __bfloat162float(h));
}

// ====================== prep kernels ======================
__global__ void k_init(const int* __restrict__ cap, const float* __restrict__ emb)
{
    int i = blockIdx.x * blockDim.x + threadIdx.x;   // 3200*512 threads
    if (i < Bz * DEC) g_h[i] = 0.f;
    int d = i & 511;
    int r = i >> 9;            // t*B + b
    int t = r >> 6;
    int b = r & 63;
    int tok = cap[b * Tz + t];
    split_store(emb[(size_t)tok * EMBD + d], g_Ahi + XE_OFF, g_Alo + XE_OFF, (size_t)i);
}

// W_ih[:,512:] and W_hh -> bf16 hi/lo [j][k]; also W_daT
__global__ void k_prepW(const float* __restrict__ W_ih, const float* __restrict__ W_hh,
                        const float* __restrict__ W_da)
{
    int i = blockIdx.x * blockDim.x + threadIdx.x;
    if (i < ATTD * DEC) {                     // W_da [512][256] -> [256][512]
        int k = i >> 8, j = i & 255;
        g_WdaT[j * DEC + k] = W_da[i];
    }
    if (i >= 2 * H3 * DEC) return;
    int mat = i / (H3 * DEC);
    int rem = i - mat * (H3 * DEC);
    int j = rem >> 9, k = rem & 511;
    float x = (mat == 0) ? W_ih[j * (EMBD + DEC) + EMBD + k] : W_hh[j * DEC + k];
    split_store(x, g_Whi, g_Wlo, (size_t)i);
}

__global__ void k_split(const float* __restrict__ src, bf16* hi, bf16* lo, int n)
{
    int i = blockIdx.x * blockDim.x + threadIdx.x;
    if (i < n) split_store(src[i], hi, lo, (size_t)i);
}

__global__ void k_split_strided(const float* __restrict__ src, bf16* hi, bf16* lo,
                                int rows, int cols, int srcStride)
{
    int i = blockIdx.x * blockDim.x + threadIdx.x;
    if (i >= rows * cols) return;
    int r = i / cols, c = i - r * cols;
    split_store(src[(size_t)r * srcStride + c], hi, lo, (size_t)i);
}

__global__ void k_transpose_split(const float* __restrict__ src, bf16* hi, bf16* lo,
                                  int Ksrc, int Nsrc)
{
    int i = blockIdx.x * blockDim.x + threadIdx.x;
    if (i >= Ksrc * Nsrc) return;
    int k = i / Nsrc, n = i - k * Nsrc;
    split_store(src[i], hi, lo, (size_t)n * Ksrc + k);
}

// W_fc [512][10000] -> fp16 [n][k]
__global__ void k_transpose_half(const float* __restrict__ src, half* dst, int Ksrc, int Nsrc)
{
    int i = blockIdx.x * blockDim.x + threadIdx.x;
    if (i >= Ksrc * Nsrc) return;
    int k = i / Nsrc, n = i - k * Nsrc;
    dst[(size_t)n * Ksrc + k] = __float2half(src[i]);
}

// ====================== 3-term bf16 pipelined GEMM ======================
#define SSTRIDE  72
#define ATILE    (128 * SSTRIDE)
#define ATILE2   (ATILE * 2)          // 18432 bytes / region
#define STAGEB   (4 * ATILE2)         // 73728
#define MMA_SMEM (2 * STAGEB)         // 147456

__global__ __launch_bounds__(256) void k_mma_gemm(
    const bf16* __restrict__ Ahi, const bf16* __restrict__ Alo,
    const bf16* __restrict__ Bhi, const bf16* __restrict__ Blo,
    const float* __restrict__ bias, float* __restrict__ C,
    int M, int N, int K)
{
    extern __shared__ bf16 sm[];
    const int tid  = threadIdx.x;
    const int wid  = tid >> 5, lane = tid & 31;
    const int wm   = wid >> 1, wn = wid & 1;
    const int mb   = blockIdx.y << 7, nb = blockIdx.x << 7;
    const uint32_t sbase = smem_to_u32(sm);
    const int lrow = lane & 15, lcol = (lane >> 4) * 8;

    uint32_t oA[2], oB[4];
    #pragma unroll
    for (int mi = 0; mi < 2; mi++)
        oA[mi] = (uint32_t)(((wm * 32 + mi * 16 + lrow) * SSTRIDE + lcol) * 2);
    #pragma unroll
    for (int nj = 0; nj < 4; nj++)
        oB[nj] = (uint32_t)(2 * ATILE2 + ((wn * 64 + nj * 16 + lrow) * SSTRIDE + lcol) * 2);

    const int rload = tid >> 3, gload = tid & 7;
    float acc[2][8][4] = {};
    const int nchunks = K >> 6;

    auto issue = [&](int c, int s) {
        const int k0 = c << 6;
        const uint32_t sb = sbase + (uint32_t)s * STAGEB;
        #pragma unroll
        for (int u = 0; u < 4; u++) {
            int r = rload + u * 32;
            uint32_t so = (uint32_t)((r * SSTRIDE + gload * 8) * 2);
            int ra = mb + r;
            unsigned za = (ra < M) ? 16u : 0u;
            if (ra >= M) ra = 0;
            CP16(sb + so,          Ahi + (size_t)ra * K + k0 + gload * 8, za);
            CP16(sb + ATILE2 + so, Alo + (size_t)ra * K + k0 + gload * 8, za);
            int rb = nb + r;
            unsigned zb = (rb < N) ? 16u : 0u;
            if (rb >= N) rb = 0;
            CP16(sb + 2 * ATILE2 + so, Bhi + (size_t)rb * K + k0 + gload * 8, zb);
            CP16(sb + 3 * ATILE2 + so, Blo + (size_t)rb * K + k0 + gload * 8, zb);
        }
    };

    issue(0, 0); CP_COMMIT();

    for (int c = 0; c < nchunks; c++) {
        if (c + 1 < nchunks) { issue(c + 1, (c + 1) & 1); CP_COMMIT(); CP_WAIT1(); }
        else                 { CP_WAIT0(); }
        __syncthreads();

        const uint32_t sb = sbase + (uint32_t)(c & 1) * STAGEB;
        #pragma unroll
        for (int ks = 0; ks < 4; ks++) {
            const uint32_t kb = ks * 32;
            uint32_t ah[2][4], al[2][4], bh[4][4], bl[4][4];
            #pragma unroll
            for (int mi = 0; mi < 2; mi++) {
                LDSM_X4(ah[mi], sb + oA[mi] + kb);
                LDSM_X4(al[mi], sb + ATILE2 + oA[mi] + kb);
            }
            #pragma unroll
            for (int nj = 0; nj < 4; nj++) {
                LDSM_X4(bh[nj], sb + oB[nj] + kb);
                LDSM_X4(bl[nj], sb + ATILE2 + oB[nj] + kb);
            }
            #pragma unroll
            for (int mi = 0; mi < 2; mi++) {
                #pragma unroll
                for (int nj = 0; nj < 4; nj++) {
                    MMA16816(acc[mi][nj * 2 + 0], ah[mi], bh[nj][0], bh[nj][2]);
                    MMA16816(acc[mi][nj * 2 + 1], ah[mi], bh[nj][1], bh[nj][3]);
                    MMA16816(acc[mi][nj * 2 + 0], ah[mi], bl[nj][0], bl[nj][2]);
                    MMA16816(acc[mi][nj * 2 + 1], ah[mi], bl[nj][1], bl[nj][3]);
                    MMA16816(acc[mi][nj * 2 + 0], al[mi], bh[nj][0], bh[nj][2]);
                    MMA16816(acc[mi][nj * 2 + 1], al[mi], bh[nj][1], bh[nj][3]);
                }
            }
        }
        __syncthreads();
    }

    #pragma unroll
    for (int mi = 0; mi < 2; mi++) {
        #pragma unroll
        for (int half_ = 0; half_ < 2; half_++) {
            int row = mb + wm * 32 + mi * 16 + (lane >> 2) + half_ * 8;
            if (row >= M) continue;
            size_t rb = (size_t)row * N;
            #pragma unroll
            for (int nf = 0; nf < 8; nf++) {
                int col = nb + wn * 64 + nf * 8 + (lane & 3) * 2;
                if (col < N) {
                    float2 v;
                    v.x = acc[mi][nf][half_ * 2 + 0] + bias[col];
                    v.y = acc[mi][nf][half_ * 2 + 1] + bias[col + 1];
                    *reinterpret_cast<float2*>(C + rb + col) = v;
                }
            }
        }
    }
}

// ====================== single-term fp16 pipelined GEMM (fc) ======================
#define H_STAGEB (2 * ATILE2)          // 36864
#define H_SMEM   (2 * H_STAGEB)       // 73728

__global__ __launch_bounds__(256) void k_gemm_h(
    const half* __restrict__ A, const half* __restrict__ B,
    const float* __restrict__ bias, float* __restrict__ C,
    int M, int N, int K)
{
    extern __shared__ half smh[];
    const int tid  = threadIdx.x;
    const int wid  = tid >> 5, lane = tid & 31;
    const int wm   = wid >> 1, wn = wid & 1;
    const int mb   = blockIdx.y << 7, nb = blockIdx.x << 7;
    const uint32_t sbase = smem_to_u32(smh);
    const int lrow = lane & 15, lcol = (lane >> 4) * 8;

    uint32_t oA[2], oB[4];
    #pragma unroll
    for (int mi = 0; mi < 2; mi++)
        oA[mi] = (uint32_t)(((wm * 32 + mi * 16 + lrow) * SSTRIDE + lcol) * 2);
    #pragma unroll
    for (int nj = 0; nj < 4; nj++)
        oB[nj] = (uint32_t)(ATILE2 + ((wn * 64 + nj * 16 + lrow) * SSTRIDE + lcol) * 2);

    const int rload = tid >> 3, gload = tid & 7;
    float acc[2][8][4] = {};
    const int nchunks = K >> 6;

    auto issue = [&](int c, int s) {
        const int k0 = c << 6;
        const uint32_t sb = sbase + (uint32_t)s * H_STAGEB;
        #pragma unroll
        for (int u = 0; u < 4; u++) {
            int r = rload + u * 32;
            uint32_t so = (uint32_t)((r * SSTRIDE + gload * 8) * 2);
            int ra = mb + r;
            unsigned za = (ra < M) ? 16u : 0u;
            if (ra >= M) ra = 0;
            CP16(sb + so, A + (size_t)ra * K + k0 + gload * 8, za);
            int rb = nb + r;
            unsigned zb = (rb < N) ? 16u : 0u;
            if (rb >= N) rb = 0;
            CP16(sb + ATILE2 + so, B + (size_t)rb * K + k0 + gload * 8, zb);
        }
    };

    issue(0, 0); CP_COMMIT();

    for (int c = 0; c < nchunks; c++) {
        if (c + 1 < nchunks) { issue(c + 1, (c + 1) & 1); CP_COMMIT(); CP_WAIT1(); }
        else                 { CP_WAIT0(); }
        __syncthreads();

        const uint32_t sb = sbase + (uint32_t)(c & 1) * H_STAGEB;
        #pragma unroll
        for (int ks = 0; ks < 4; ks++) {
            const uint32_t kb = ks * 32;
            uint32_t ah[2][4], bh[4][4];
            #pragma unroll
            for (int mi = 0; mi < 2; mi++) LDSM_X4(ah[mi], sb + oA[mi] + kb);
            #pragma unroll
            for (int nj = 0; nj < 4; nj++) LDSM_X4(bh[nj], sb + oB[nj] + kb);
            #pragma unroll
            for (int mi = 0; mi < 2; mi++) {
                #pragma unroll
                for (int nj = 0; nj < 4; nj++) {
                    MMA16816H(acc[mi][nj * 2 + 0], ah[mi], bh[nj][0], bh[nj][2]);
                    MMA16816H(acc[mi][nj * 2 + 1], ah[mi], bh[nj][1], bh[nj][3]);
                }
            }
        }
        __syncthreads();
    }

    // epilogue, fc remap: row = t*B+b -> out[(b*T+t)*N + col]
    #pragma unroll
    for (int mi = 0; mi < 2; mi++) {
        #pragma unroll
        for (int half_ = 0; half_ < 2; half_++) {
            int row = mb + wm * 32 + mi * 16 + (lane >> 2) + half_ * 8;
            if (row >= M) continue;
            int tq = row >> 6, bb = row & 63;
            size_t rb = (size_t)(bb * Tz + tq) * N;
            #pragma unroll
            for (int nf = 0; nf < 8; nf++) {
                int col = nb + wn * 64 + nf * 8 + (lane & 3) * 2;
                if (col < N) {
                    float2 v;
                    v.x = acc[mi][nf][half_ * 2 + 0] + bias[col];
                    v.y = acc[mi][nf][half_ * 2 + 1] + bias[col + 1];
                    *reinterpret_cast<float2*>(C + rb + col) = v;
                }
            }
        }
    }
}

// ====================== per-step GEMM: bf16 3-term, cp.async, split-K 2 ======================
// grid (12, 2, 2): nb over H3, mat {gi_c, gh}, kz K-half. tile 64x128, K=256 per block.
#define SG_A2    (64 * SSTRIDE * 2)            // 9216
#define SG_B2    (128 * SSTRIDE * 2)           // 18432
#define SG_STAGE (2 * SG_A2 + 2 * SG_B2)       // 55296
#define SG_SMEM  (2 * SG_STAGE)                // 110592

__global__ __launch_bounds__(256) void k_stepgemm_mma()
{
    extern __shared__ bf16 sm[];
    const int tid = threadIdx.x, wid = tid >> 5, lane = tid & 31;
    const int wm = wid >> 2, wn = wid & 3;
    const int nb = blockIdx.x << 7;
    const int mat = blockIdx.y;
    const int kz = blockIdx.z;
    const int kbase = kz << 8;
    const bf16* Ahi_ = mat ? g_hhi : g_chi;
    const bf16* Alo_ = mat ? g_hlo : g_clo;
    const bf16* Bh_  = g_Whi + (size_t)mat * H3 * DEC;
    const bf16* Bl_  = g_Wlo + (size_t)mat * H3 * DEC;
    float* out = g_part + (size_t)((mat * 2 + kz) * Bz) * H3;

    const uint32_t sbase = smem_to_u32(sm);
    const uint32_t oAl0 = SG_A2, oBh0 = 2 * SG_A2, oBl0 = 2 * SG_A2 + SG_B2;
    const int lrow = lane & 15, lcol = (lane >> 4) * 8;
    uint32_t oA[2], oB[2];
    #pragma unroll
    for (int mi = 0; mi < 2; mi++)
        oA[mi] = (uint32_t)(((wm * 32 + mi * 16 + lrow) * SSTRIDE + lcol) * 2);
    #pragma unroll
    for (int nj = 0; nj < 2; nj++)
        oB[nj] = (uint32_t)(((wn * 32 + nj * 16 + lrow) * SSTRIDE + lcol) * 2);

    float acc[2][4][4] = {};
    const int rlA = tid >> 3, gl = tid & 7;    // rlA 0..31

    auto issue = [&](int c, int s) {
        const int k0 = kbase + (c << 6);
        const uint32_t sb = sbase + (uint32_t)s * SG_STAGE;
        #pragma unroll
        for (int u = 0; u < 2; u++) {          // A: 64 rows
            int r = rlA + u * 32;
            uint32_t so = (uint32_t)((r * SSTRIDE + gl * 8) * 2);
            size_t gi = (size_t)r * DEC + k0 + gl * 8;
            CP16(sb + so,        Ahi_ + gi, 16u);
            CP16(sb + oAl0 + so, Alo_ + gi, 16u);
        }
        #pragma unroll
        for (int u = 0; u < 4; u++) {          // B: 128 rows
            int r = rlA + u * 32;
            uint32_t so = (uint32_t)((r * SSTRIDE + gl * 8) * 2);
            size_t gi = (size_t)(nb + r) * DEC + k0 + gl * 8;
            CP16(sb + oBh0 + so, Bh_ + gi, 16u);
            CP16(sb + oBl0 + so, Bl_ + gi, 16u);
        }
    };

    issue(0, 0); CP_COMMIT();

    for (int c = 0; c < 4; c++) {
        if (c + 1 < 4) { issue(c + 1, (c + 1) & 1); CP_COMMIT(); CP_WAIT1(); }
        else           { CP_WAIT0(); }
        __syncthreads();

        const uint32_t sb = sbase + (uint32_t)(c & 1) * SG_STAGE;
        #pragma unroll
        for (int ks = 0; ks < 4; ks++) {
            uint32_t kb = ks * 32;
            uint32_t ah[2][4], al[2][4], bh[2][4], bl[2][4];
            #pragma unroll
            for (int mi = 0; mi < 2; mi++) {
                LDSM_X4(ah[mi], sb + oA[mi] + kb);
                LDSM_X4(al[mi], sb + oAl0 + oA[mi] + kb);
            }
            #pragma unroll
            for (int nj = 0; nj < 2; nj++) {
                LDSM_X4(bh[nj], sb + oBh0 + oB[nj] + kb);
                LDSM_X4(bl[nj], sb + oBl0 + oB[nj] + kb);
            }
            #pragma unroll
            for (int mi = 0; mi < 2; mi++) {
                #pragma unroll
                for (int nj = 0; nj < 2; nj++) {
                    MMA16816(acc[mi][nj * 2 + 0], ah[mi], bh[nj][0], bh[nj][2]);
                    MMA16816(acc[mi][nj * 2 + 1], ah[mi], bh[nj][1], bh[nj][3]);
                    MMA16816(acc[mi][nj * 2 + 0], ah[mi], bl[nj][0], bl[nj][2]);
                    MMA16816(acc[mi][nj * 2 + 1], ah[mi], bl[nj][1], bl[nj][3]);
                    MMA16816(acc[mi][nj * 2 + 0], al[mi], bh[nj][0], bh[nj][2]);
                    MMA16816(acc[mi][nj * 2 + 1], al[mi], bh[nj][1], bh[nj][3]);
                }
            }
        }
        __syncthreads();
    }

    #pragma unroll
    for (int mi = 0; mi < 2; mi++) {
        #pragma unroll
        for (int half_ = 0; half_ < 2; half_++) {
            int row = wm * 32 + mi * 16 + (lane >> 2) + half_ * 8;
            #pragma unroll
            for (int nf = 0; nf < 4; nf++) {
                int col = nb + wn * 32 + nf * 8 + (lane & 3) * 2;
                float2 v;
                v.x = acc[mi][nf][half_ * 2 + 0];
                v.y = acc[mi][nf][half_ * 2 + 1];
                *reinterpret_cast<float2*>(out + (size_t)row * H3 + col) = v;
            }
        }
    }
}

// ====================== GRU combine + attention ======================
__device__ __forceinline__ float gru_update(int r, int b, int d, const float* __restrict__ b_hh)
{
    const float* gie = &g_gie[(size_t)r * H3];
    const float* p0 = &g_part[(size_t)b * H3];              // gi_c k0
    const float* p1 = &g_part[(size_t)(Bz + b) * H3];       // gi_c k1
    const float* q0 = &g_part[(size_t)(2 * Bz + b) * H3];   // gh k0
    const float* q1 = &g_part[(size_t)(3 * Bz + b) * H3];   // gh k1
    float ir  = gie[d]           + p0[d]           + p1[d];
    float iz  = gie[DEC + d]     + p0[DEC + d]     + p1[DEC + d];
    float in_ = gie[2 * DEC + d] + p0[2 * DEC + d] + p1[2 * DEC + d];
    float hr  = b_hh[d]           + q0[d]           + q1[d];
    float hz  = b_hh[DEC + d]     + q0[DEC + d]     + q1[DEC + d];
    float hn  = b_hh[2 * DEC + d] + q0[2 * DEC + d] + q1[2 * DEC + d];
    float rr = 1.f / (1.f + expf(-(ir + hr)));
    float zz = 1.f / (1.f + expf(-(iz + hz)));
    float nn = tanhf(in_ + rr * hn);
    float hp = g_h[b * DEC + d];
    return (1.f - zz) * nn + zz * hp;
}

// fused gates(t-1) -> h_t -> Bahdanau attention. grid 32 blocks x 2 batch rows.
__global__ __launch_bounds__(256) void k_att(
    int t,
    const float* __restrict__ b_da,
    const float* __restrict__ W_fa, const float* __restrict__ b_hh)
{
    __shared__ float sh_h [2][DEC];
    __shared__ float sh_a2[2][ATTD];
    __shared__ float sh_sc[2][64];
    const int tid = threadIdx.x;
    const int b0 = blockIdx.x << 1;

    if (t > 0) {
        #pragma unroll
        for (int ii = 0; ii < 4; ii++) {
            int idx = tid + (ii << 8);          // 0..1023
            int bi = idx >> 9, d = idx & 511;
            int b = b0 + bi;
            int r = (t - 1) * Bz + b;
            float hv = gru_update(r, b, d, b_hh);
            sh_h[bi][d] = hv;
            g_h[b * DEC + d] = hv;
            bf16 hh = __float2bfloat16(hv);
            g_hhi[b * DEC + d] = hh;
            g_hlo[b * DEC + d] = __float2bfloat16(hv - __bfloat162float(hh));
            g_Hs16[(size_t)r * DEC + d] = __float2half(hv);
        }
    } else {
        bf16 zb = __float2bfloat16(0.f);
        #pragma unroll
        for (int ii = 0; ii < 4; ii++) {
            int idx = tid + (ii << 8);
            int bi = idx >> 9, d = idx & 511;
            sh_h[bi][d] = 0.f;
            g_hhi[(b0 + bi) * DEC + d] = zb;
            g_hlo[(b0 + bi) * DEC + d] = zb;
        }
    }
    __syncthreads();

    // att2[bi][j] = h[bi] @ W_da[:,j] + b_da[j]  via W_daT rows (float4-contiguous)
    {
        int j = tid;
        const float4* wrow = reinterpret_cast<const float4*>(g_WdaT + (size_t)j * DEC);
        float a0 = b_da[j], a1 = a0;
        #pragma unroll 8
        for (int kk = 0; kk < DEC / 4; kk++) {
            float4 w  = wrow[kk];
            float4 h0 = *reinterpret_cast<const float4*>(&sh_h[0][kk * 4]);
            float4 h1 = *reinterpret_cast<const float4*>(&sh_h[1][kk * 4]);
            a0 += w.x * h0.x + w.y * h0.y + w.z * h0.z + w.w * h0.w;
            a1 += w.x * h1.x + w.y * h1.y + w.z * h1.z + w.w * h1.w;
        }
        sh_a2[0][j] = a0; sh_a2[1][j] = a1;
    }
    __syncthreads();

    // scores
    {
        int warp = tid >> 5, lane = tid & 31;
        float wfa[8];
        #pragma unroll
        for (int q = 0; q < 8; q++) wfa[q] = W_fa[lane + 32 * q];
        for (int p = warp; p < 2 * Lz; p += 8) {
            int bi = (p >= Lz) ? 1 : 0;
            int l = p - bi * Lz;
            const float* arow = &g_att1[((size_t)(b0 + bi) * Lz + l) * ATTD];
            float s = 0.f;
            #pragma unroll
            for (int q = 0; q < 8; q++) {
                int j = lane + 32 * q;
                s += tanhf(arow[j] + sh_a2[bi][j]) * wfa[q];
            }
            #pragma unroll
            for (int o = 16; o; o >>= 1) s += __shfl_xor_sync(0xffffffffu, s, o);
            if (lane == 0) sh_sc[bi][l] = s;
        }
    }
    __syncthreads();

    // softmax over L=49
    if (tid < 2) {
        float mx = -1e30f;
        for (int l = 0; l < Lz; l++) mx = fmaxf(mx, sh_sc[tid][l]);
        float sum = 0.f;
        for (int l = 0; l < Lz; l++) { float e = expf(sh_sc[tid][l] - mx); sh_sc[tid][l] = e; sum += e; }
        float inv = 1.f / sum;
        for (int l = 0; l < Lz; l++) sh_sc[tid][l] *= inv;
    }
    __syncthreads();

    // context -> bf16 hi/lo split
    {
        int d = tid;
        #pragma unroll
        for (int bi = 0; bi < 2; bi++) {
            const float* erow = &g_enc[(size_t)(b0 + bi) * Lz * DEC];
            float c0 = 0.f, c1 = 0.f;
            #pragma unroll 7
            for (int l = 0; l < Lz; l++) {
                float al = sh_sc[bi][l];
                c0 += al * erow[l * DEC + d];
                c1 += al * erow[l * DEC + 256 + d];
            }
            int b = b0 + bi;
            split_store(c0, g_chi, g_clo, (size_t)b * DEC + d);
            split_store(c1, g_chi, g_clo, (size_t)b * DEC + 256 + d);
        }
    }
}

// final step's gate combine (t = T-1)
__global__ void k_gates(int t, const float* __restrict__ b_hh)
{
    int b = blockIdx.x, d = threadIdx.x;
    int r = t * Bz + b;
    float hv = gru_update(r, b, d, b_hh);
    g_Hs16[(size_t)r * DEC + d] = __float2half(hv);
}

// ====================== launcher ======================
extern "C" void kernel_launch(void* const* d_in, const int* in_sizes, int n_in,
                              void* d_out, int out_size)
{
    (void)in_sizes; (void)n_in; (void)out_size;
    const float* spatial = (const float*)d_in[0];
    const int*   cap     = (const int*)  d_in[1];
    const float* W_feat  = (const float*)d_in[2];
    const float* b_feat  = (const float*)d_in[3];
    const float* W_ea    = (const float*)d_in[4];
    const float* b_ea    = (const float*)d_in[5];
    const float* W_da    = (const float*)d_in[6];
    const float* b_da    = (const float*)d_in[7];
    const float* W_fa    = (const float*)d_in[8];
    /* b_fa (d_in[9]) softmax-invariant */
    const float* emb     = (const float*)d_in[10];
    const float* W_ih    = (const float*)d_in[11];
    const float* W_hh    = (const float*)d_in[12];
    const float* b_ih    = (const float*)d_in[13];
    const float* b_hh    = (const float*)d_in[14];
    const float* W_fc    = (const float*)d_in[15];
    const float* b_fc    = (const float*)d_in[16];
    float* out = (float*)d_out;

    float *p_enc, *p_att1, *p_gie;
    bf16 *p_ahi, *p_alo, *p_bhi, *p_blo;
    half *p_hs16, *p_wfc16;
    cudaGetSymbolAddress((void**)&p_enc,   g_enc);
    cudaGetSymbolAddress((void**)&p_att1,  g_att1);
    cudaGetSymbolAddress((void**)&p_gie,   g_gie);
    cudaGetSymbolAddress((void**)&p_ahi,   g_Ahi);
    cudaGetSymbolAddress((void**)&p_alo,   g_Alo);
    cudaGetSymbolAddress((void**)&p_bhi,   g_Bhi);
    cudaGetSymbolAddress((void**)&p_blo,   g_Blo);
    cudaGetSymbolAddress((void**)&p_hs16,  g_Hs16);
    cudaGetSymbolAddress((void**)&p_wfc16, g_Wfc16);

    cudaFuncSetAttribute(k_mma_gemm, cudaFuncAttributeMaxDynamicSharedMemorySize, MMA_SMEM);
    cudaFuncSetAttribute(k_gemm_h, cudaFuncAttributeMaxDynamicSharedMemorySize, H_SMEM);
    cudaFuncSetAttribute(k_stepgemm_mma, cudaFuncAttributeMaxDynamicSharedMemorySize, SG_SMEM);

    const int SM = Bz * Lz;      // 3136
    const int SR = Tz * Bz;      // 3200

    // setup
    k_init<<<SR, EMBD>>>(cap, emb);
    k_prepW<<<(2 * H3 * DEC + 255) / 256, 256>>>(W_ih, W_hh, W_da);

    // ---- enc = spatial @ W_feat + b_feat  [3136, 512] (3-term bf16) ----
    k_split<<<(SM * ENCD + 255) / 256, 256>>>(spatial, p_ahi, p_alo, SM * ENCD);
    k_transpose_split<<<(ENCD * DEC + 255) / 256, 256>>>(W_feat, p_bhi, p_blo, ENCD, DEC);
    k_mma_gemm<<<dim3(DEC / 128, (SM + 127) / 128), 256, MMA_SMEM>>>(
        p_ahi, p_alo, p_bhi, p_blo, b_feat, p_enc, SM, DEC, ENCD);

    // ---- att1 = enc @ W_ea + b_ea  [3136, 256] (3-term bf16) ----
    k_split<<<(SM * DEC + 255) / 256, 256>>>(p_enc, p_ahi, p_alo, SM * DEC);
    k_transpose_split<<<(DEC * ATTD + 255) / 256, 256>>>(W_ea, p_bhi, p_blo, DEC, ATTD);
    k_mma_gemm<<<dim3(ATTD / 128, (SM + 127) / 128), 256, MMA_SMEM>>>(
        p_ahi, p_alo, p_bhi, p_blo, b_ea, p_att1, SM, ATTD, DEC);

    // ---- gie = Xemb @ W_ih[:, :512]^T + b_ih  [3200, 1536] (3-term bf16) ----
    k_split_strided<<<(H3 * DEC + 255) / 256, 256>>>(W_ih, p_bhi, p_blo, H3, DEC, EMBD + DEC);
    k_mma_gemm<<<dim3(H3 / 128, SR / 128), 256, MMA_SMEM>>>(
        p_ahi + XE_OFF, p_alo + XE_OFF, p_bhi, p_blo, b_ih, p_gie, SR, H3, DEC);

    // ---- sequential decode ----
    for (int t = 0; t < Tz; t++) {
        k_att<<<32, 256>>>(t, b_da, W_fa, b_hh);
        k_stepgemm_mma<<<dim3(12, 2, 2), 256, SG_SMEM>>>();
    }
    k_gates<<<Bz, DEC>>>(Tz - 1, b_hh);

    // ---- fc: logits = Hseq @ W_fc + b_fc (single-term fp16), remap [B,T,V] ----
    k_transpose_half<<<(DEC * VOC + 255) / 256, 256>>>(W_fc, p_wfc16, DEC, VOC);
    k_gemm_h<<<dim3((VOC + 127) / 128, SR / 128), 256, H_SMEM>>>(
        p_hs16, p_wfc16, b_fc, out, SR, VOC, DEC);
}